// round 7
// baseline (speedup 1.0000x reference)
#include <cuda_runtime.h>
#include <cuda_bf16.h>
#include <cstdint>

// Problem constants (fixed by the dataset)
#define BATCH   4
#define SEQ     4096
#define HID     2048
#define NHEADS  16
#define HDIM    128
#define FDIM    64
#define MROWS   (BATCH * SEQ)          // 16384
#define M2      (MROWS * NHEADS)       // 262144
#define BHEADS  (BATCH * NHEADS)       // 64
#define KVCH    16
#define KVELEM  (BHEADS * FDIM * HDIM) // 524288
#define NQP     (NHEADS * FDIM)        // 1024

// ---------------- scratch (static device globals; no allocation) -----------
__device__ float g_V[(size_t)MROWS * HID];
__device__ float g_qp[(size_t)M2 * FDIM];
__device__ float g_kp[(size_t)M2 * FDIM];
__device__ float g_kvpart[(size_t)KVCH * KVELEM];
__device__ float g_kv[KVELEM];
__device__ float g_kspart[KVCH * BHEADS * FDIM];
__device__ float g_ksum[BHEADS * FDIM];
__device__ float g_bqc[NQP];
__device__ float g_bkc[NQP];
// bf16 hi/lo planes
__device__ __nv_bfloat16 g_qh[(size_t)MROWS * HID],  g_ql[(size_t)MROWS * HID];
__device__ __nv_bfloat16 g_kh[(size_t)MROWS * HID],  g_kl[(size_t)MROWS * HID];
__device__ __nv_bfloat16 g_vh[(size_t)MROWS * HID],  g_vl[(size_t)MROWS * HID];
__device__ __nv_bfloat16 g_ah[(size_t)MROWS * HID],  g_al[(size_t)MROWS * HID];
__device__ __nv_bfloat16 g_Wvh[(size_t)HID * HID],   g_Wvl[(size_t)HID * HID];
__device__ __nv_bfloat16 g_Woh[(size_t)HID * HID],   g_Wol[(size_t)HID * HID];
__device__ __nv_bfloat16 g_Wqch[(size_t)NQP * HID],  g_Wqcl[(size_t)NQP * HID];
__device__ __nv_bfloat16 g_Wkch[(size_t)NQP * HID],  g_Wkcl[(size_t)NQP * HID];

// =========================== helpers =======================================
__device__ __forceinline__ uint32_t smem_u32(const void* p) {
    uint32_t a;
    asm("{ .reg .u64 t; cvta.to.shared.u64 t, %1; cvt.u32.u64 %0, t; }"
        : "=r"(a) : "l"(p));
    return a;
}
#define SMEM_SWIZZLE_128B(off) ((off) ^ (((off) >> 3) & 0x70))

__device__ __forceinline__ void cp16(uint32_t dst, const void* src) {
    asm volatile("cp.async.cg.shared.global [%0], [%1], 16;"
                 :: "r"(dst), "l"(src) : "memory");
}
#define CP_COMMIT() asm volatile("cp.async.commit_group;" ::: "memory")
#define CP_WAIT1()  asm volatile("cp.async.wait_group 1;" ::: "memory")

__device__ __forceinline__ void ldsm_x4(uint32_t& r0, uint32_t& r1,
                                        uint32_t& r2, uint32_t& r3,
                                        uint32_t addr) {
    asm volatile("ldmatrix.sync.aligned.m8n8.x4.shared.b16 {%0,%1,%2,%3}, [%4];"
                 : "=r"(r0), "=r"(r1), "=r"(r2), "=r"(r3) : "r"(addr));
}
__device__ __forceinline__ void mma_bf16(float* d, const uint32_t* a,
                                         const uint32_t* b) {
    asm volatile(
        "mma.sync.aligned.m16n8k16.row.col.f32.bf16.bf16.f32 "
        "{%0,%1,%2,%3}, {%4,%5,%6,%7}, {%8,%9}, {%0,%1,%2,%3};"
        : "+f"(d[0]), "+f"(d[1]), "+f"(d[2]), "+f"(d[3])
        : "r"(a[0]), "r"(a[1]), "r"(a[2]), "r"(a[3]), "r"(b[0]), "r"(b[1]));
}
__device__ __forceinline__ void split_pack(float x, float y, uint32_t& h, uint32_t& l) {
    __nv_bfloat16 hx = __float2bfloat16(x);
    __nv_bfloat16 hy = __float2bfloat16(y);
    h = (uint32_t)__bfloat16_as_ushort(hx) |
        ((uint32_t)__bfloat16_as_ushort(hy) << 16);
    __nv_bfloat16 lx = __float2bfloat16(x - __bfloat162float(hx));
    __nv_bfloat16 ly = __float2bfloat16(y - __bfloat162float(hy));
    l = (uint32_t)__bfloat16_as_ushort(lx) |
        ((uint32_t)__bfloat16_as_ushort(ly) << 16);
}

// ===========================================================================
// fp32 -> bf16 hi/lo plane conversion (8 elements / thread)
// ===========================================================================
__global__ void __launch_bounds__(256)
conv_kernel(const float* __restrict__ src, int sel, int n8)
{
    __nv_bfloat16 *dh, *dl;
    switch (sel) {
        case 0: dh = g_qh;  dl = g_ql;  break;
        case 1: dh = g_kh;  dl = g_kl;  break;
        case 2: dh = g_vh;  dl = g_vl;  break;
        case 3: dh = g_Wvh; dl = g_Wvl; break;
        default: dh = g_Woh; dl = g_Wol; break;
    }
    int i = blockIdx.x * 256 + threadIdx.x;
    if (i >= n8) return;
    const float4* s4 = (const float4*)src + (size_t)i * 2;
    float4 v0 = s4[0], v1 = s4[1];
    uint32_t h[4], l[4];
    split_pack(v0.x, v0.y, h[0], l[0]);
    split_pack(v0.z, v0.w, h[1], l[1]);
    split_pack(v1.x, v1.y, h[2], l[2]);
    split_pack(v1.z, v1.w, h[3], l[3]);
    *(uint4*)(dh + (size_t)i * 8) = make_uint4(h[0], h[1], h[2], h[3]);
    *(uint4*)(dl + (size_t)i * 8) = make_uint4(l[0], l[1], l[2], l[3]);
}

// ===========================================================================
// Tensor-core GEMM, bf16 3-term split, cp.async double-buffered.
//   C[M,N] = A[M,2048] @ W[N,2048]^T + bias [,relu][,row-mask]
// 256x128 tile, K-chunk 64 (128B rows, SW128), 512 threads (16 warps),
// 1 CTA/SM, 192KB smem.
// ===========================================================================
#define TILE_K   64
#define CHUNKS   (HID / TILE_K)   // 32
#define OFF_AH   0
#define OFF_AL   32768
#define OFF_BH   65536
#define OFF_BL   81920
#define STG      98304            // 96KB per stage (A 64KB + B 32KB)
#define NSTAGE   2
#define GSMEM    (NSTAGE * STG)   // 196608

__device__ __forceinline__ void stage_load(
    uint32_t sbuf, const __nv_bfloat16* Abh, const __nv_bfloat16* Abl,
    const __nv_bfloat16* Bbh, const __nv_bfloat16* Bbl, int k0, int tid)
{
    // A: 256 rows x 64 cols, hi+lo
    #pragma unroll
    for (int i = 0; i < 4; i++) {
        int idx = tid + 512 * i;          // 0..2047
        int r   = idx >> 3;               // 0..255
        int s   = (idx & 7) * 8;          // 0..56
        uint32_t off = SMEM_SWIZZLE_128B((uint32_t)(r * 128 + s * 2));
        size_t g = (size_t)r * HID + k0 + s;
        cp16(sbuf + OFF_AH + off, Abh + g);
        cp16(sbuf + OFF_AL + off, Abl + g);
    }
    // B: 128 rows x 64 cols, hi+lo
    #pragma unroll
    for (int i = 0; i < 2; i++) {
        int idx = tid + 512 * i;          // 0..1023
        int r   = idx >> 3;               // 0..127
        int s   = (idx & 7) * 8;
        uint32_t off = SMEM_SWIZZLE_128B((uint32_t)(r * 128 + s * 2));
        size_t g = (size_t)r * HID + k0 + s;
        cp16(sbuf + OFF_BH + off, Bbh + g);
        cp16(sbuf + OFF_BL + off, Bbl + g);
    }
}

__global__ void __launch_bounds__(512, 1)
gemm_tc(int asel, int wsel, const float* __restrict__ bext, int bsel,
        float* __restrict__ Cext, int csel,
        const float* __restrict__ mask, int flags, int N)
{
    extern __shared__ char smem[];
    const __nv_bfloat16 *Ah, *Al, *Wh, *Wl;
    switch (asel) {
        case 0: Ah = g_qh; Al = g_ql; break;
        case 1: Ah = g_kh; Al = g_kl; break;
        case 2: Ah = g_vh; Al = g_vl; break;
        default: Ah = g_ah; Al = g_al; break;
    }
    switch (wsel) {
        case 0: Wh = g_Wqch; Wl = g_Wqcl; break;
        case 1: Wh = g_Wkch; Wl = g_Wkcl; break;
        case 2: Wh = g_Wvh;  Wl = g_Wvl;  break;
        default: Wh = g_Woh; Wl = g_Wol; break;
    }
    const float* bias = (bsel == 0) ? g_bqc : (bsel == 1) ? g_bkc : bext;
    float* C = (csel == 0) ? g_qp : (csel == 1) ? g_kp : (csel == 2) ? g_V : Cext;

    const uint32_t sb = smem_u32(smem);
    const int tid  = threadIdx.x;
    const int lane = tid & 31;
    const int wid  = tid >> 5;
    const int wm   = wid >> 2;         // 0..3  (M: 4 x 64)
    const int wn   = wid & 3;          // 0..3  (N: 4 x 32)
    const int bn   = blockIdx.x * 128;
    const int bm   = blockIdx.y * 256;

    const __nv_bfloat16* Abh = Ah + (size_t)bm * HID;
    const __nv_bfloat16* Abl = Al + (size_t)bm * HID;
    const __nv_bfloat16* Bbh = Wh + (size_t)bn * HID;
    const __nv_bfloat16* Bbl = Wl + (size_t)bn * HID;

    const uint32_t a_row  = (uint32_t)(wm * 64 + (lane & 15));
    const uint32_t a_kofs = (uint32_t)((lane >> 4) * 16);
    const uint32_t b_row  = (uint32_t)(wn * 32 + (lane & 7) + ((lane & 16) >> 1));
    const uint32_t b_kofs = (uint32_t)((lane & 8) * 2);

    float acc[4][4][4];
    #pragma unroll
    for (int mf = 0; mf < 4; mf++)
        #pragma unroll
        for (int nf = 0; nf < 4; nf++)
            #pragma unroll
            for (int j = 0; j < 4; j++) acc[mf][nf][j] = 0.f;

    // prologue: both stages in flight
    stage_load(sb + 0 * STG, Abh, Abl, Bbh, Bbl, 0, tid);
    CP_COMMIT();
    stage_load(sb + 1 * STG, Abh, Abl, Bbh, Bbl, TILE_K, tid);
    CP_COMMIT();

    #pragma unroll 1
    for (int c = 0; c < CHUNKS; c++) {
        CP_WAIT1();            // stage c landed (only group c+1 may remain)
        __syncthreads();

        const uint32_t sbase = sb + (c & 1) * STG;
        #pragma unroll
        for (int ks = 0; ks < 4; ks++) {
            const uint32_t kb = (uint32_t)(ks * 32);
            uint32_t bhf[8], blf[8];
            #pragma unroll
            for (int nf2 = 0; nf2 < 2; nf2++) {
                uint32_t off = SMEM_SWIZZLE_128B(
                    (b_row + nf2 * 16) * 128 + kb + b_kofs);
                ldsm_x4(bhf[nf2*4+0], bhf[nf2*4+1], bhf[nf2*4+2], bhf[nf2*4+3],
                        sbase + OFF_BH + off);
                ldsm_x4(blf[nf2*4+0], blf[nf2*4+1], blf[nf2*4+2], blf[nf2*4+3],
                        sbase + OFF_BL + off);
            }
            #pragma unroll
            for (int mf = 0; mf < 4; mf++) {
                uint32_t aoff = SMEM_SWIZZLE_128B(
                    (a_row + mf * 16) * 128 + kb + a_kofs);
                uint32_t ah[4], al[4];
                ldsm_x4(ah[0], ah[1], ah[2], ah[3], sbase + OFF_AH + aoff);
                ldsm_x4(al[0], al[1], al[2], al[3], sbase + OFF_AL + aoff);
                #pragma unroll
                for (int nf = 0; nf < 4; nf++) {
                    mma_bf16(acc[mf][nf], ah, &bhf[nf * 2]);   // hi*hi
                    mma_bf16(acc[mf][nf], ah, &blf[nf * 2]);   // hi*lo
                    mma_bf16(acc[mf][nf], al, &bhf[nf * 2]);   // lo*hi
                }
            }
        }

        __syncthreads();       // everyone done reading stage c
        if (c + 2 < CHUNKS)
            stage_load(sb + (c & 1) * STG, Abh, Abl, Bbh, Bbl,
                       (c + 2) * TILE_K, tid);
        CP_COMMIT();           // empty commit groups are legal no-ops
    }

    // ---- epilogue: bias [+relu][+mask] ----
    const int tq = lane >> 2;
    const int tr = lane & 3;
    float2 bv[4];
    #pragma unroll
    for (int nf = 0; nf < 4; nf++) {
        int col = bn + wn * 32 + nf * 8 + tr * 2;
        bv[nf].x = bias[col];
        bv[nf].y = bias[col + 1];
    }
    #pragma unroll
    for (int mf = 0; mf < 4; mf++) {
        #pragma unroll
        for (int half = 0; half < 2; half++) {
            int row = bm + wm * 64 + mf * 16 + tq + half * 8;
            float mv = (flags & 2) ? mask[row] : 1.0f;
            float* dst = C + (size_t)row * N + bn + wn * 32 + tr * 2;
            #pragma unroll
            for (int nf = 0; nf < 4; nf++) {
                float2 v;
                v.x = acc[mf][nf][half * 2 + 0] + bv[nf].x;
                v.y = acc[mf][nf][half * 2 + 1] + bv[nf].y;
                if (flags & 1) { v.x = fmaxf(v.x, 0.f); v.y = fmaxf(v.y, 0.f); }
                v.x *= mv; v.y *= mv;
                *(float2*)(dst + nf * 8) = v;
            }
        }
    }
}

// ===========================================================================
// Combined-weight precompute -> bf16 hi/lo planes
// ===========================================================================
__global__ void __launch_bounds__(256)
comb_kernel(const float* __restrict__ Wq, const float* __restrict__ Wqf,
            const float* __restrict__ Wk, const float* __restrict__ Wkf)
{
    const int isk = blockIdx.z;
    const float* Wbig = isk ? Wk : Wq;
    const float* Wf   = isk ? Wkf : Wqf;
    __nv_bfloat16* outh = isk ? g_Wkch : g_Wqch;
    __nv_bfloat16* outl = isk ? g_Wkcl : g_Wqcl;
    const int h  = blockIdx.y;
    const int e0 = blockIdx.x * 128;

    __shared__ float Wfs[FDIM][HDIM + 1];
    __shared__ float Ws[16][128];

    const int tid = threadIdx.x;
    for (int idx = tid; idx < FDIM * HDIM; idx += 256)
        Wfs[idx >> 7][idx & 127] = Wf[idx];

    const int f  = tid & 63;
    const int eg = tid >> 6;
    float acc[32];
    #pragma unroll
    for (int j = 0; j < 32; j++) acc[j] = 0.f;

    for (int d0 = 0; d0 < HDIM; d0 += 16) {
        __syncthreads();
        #pragma unroll
        for (int i = 0; i < 2; i++) {
            int idx = tid + 256 * i;
            int dd  = idx >> 5;
            int c4  = (idx & 31) * 4;
            *(float4*)&Ws[dd][c4] =
                *(const float4*)(Wbig + (size_t)(h * HDIM + d0 + dd) * HID + e0 + c4);
        }
        __syncthreads();
        #pragma unroll
        for (int dd = 0; dd < 16; dd++) {
            float wf = Wfs[f][d0 + dd];
            #pragma unroll
            for (int j = 0; j < 32; j++)
                acc[j] += wf * Ws[dd][eg * 32 + j];
        }
    }
    #pragma unroll
    for (int j = 0; j < 32; j++) {
        size_t idx = (size_t)(h * FDIM + f) * HID + e0 + eg * 32 + j;
        float v = acc[j];
        __nv_bfloat16 hb = __float2bfloat16(v);
        outh[idx] = hb;
        outl[idx] = __float2bfloat16(v - __bfloat162float(hb));
    }
}

__global__ void __launch_bounds__(64)
bias_comb_kernel(const float* __restrict__ bq, const float* __restrict__ Wqf,
                 const float* __restrict__ bk, const float* __restrict__ Wkf)
{
    const int isk = blockIdx.y;
    const float* b  = isk ? bk : bq;
    const float* Wf = isk ? Wkf : Wqf;
    float* out = isk ? g_bkc : g_bqc;
    const int h = blockIdx.x;
    const int f = threadIdx.x;
    float s = 0.f;
    for (int d = 0; d < HDIM; d++) s += Wf[f * HDIM + d] * b[h * HDIM + d];
    out[h * FDIM + f] = s;
}

// ===========================================================================
// kv partial + per-chunk k' column sums (deterministic split-K)
// ===========================================================================
__global__ void __launch_bounds__(256)
kv_partial_kernel()
{
    __shared__ float ks[32][FDIM];
    __shared__ float vs[32][HDIM];

    const int tid = threadIdx.x;
    const int bh  = blockIdx.y;
    const int b   = bh >> 4, h = bh & 15;
    const int s0  = blockIdx.x * (SEQ / KVCH);
    const int fg  = tid >> 4;
    const int eg  = tid & 15;

    float acc[4][8];
    #pragma unroll
    for (int i = 0; i < 4; i++)
        #pragma unroll
        for (int j = 0; j < 8; j++) acc[i][j] = 0.f;
    float ksacc = 0.f;

    for (int ss = 0; ss < SEQ / KVCH; ss += 32) {
        #pragma unroll
        for (int i = 0; i < 2; i++) {
            int idx = tid + 256 * i;
            int sr  = idx >> 4;
            int c4  = (idx & 15) * 4;
            *(float4*)&ks[sr][c4] = *(const float4*)(
                g_kp + ((size_t)(b * SEQ + s0 + ss + sr) * NHEADS + h) * FDIM + c4);
        }
        #pragma unroll
        for (int i = 0; i < 4; i++) {
            int idx = tid + 256 * i;
            int sr  = idx >> 5;
            int c4  = (idx & 31) * 4;
            *(float4*)&vs[sr][c4] = *(const float4*)(
                g_V + (size_t)(b * SEQ + s0 + ss + sr) * HID + h * HDIM + c4);
        }
        __syncthreads();

        #pragma unroll 4
        for (int s = 0; s < 32; s++) {
            float a[4];
            *(float4*)a = *(const float4*)&ks[s][fg * 4];
            float bb[8];
            *(float4*)&bb[0] = *(const float4*)&vs[s][eg * 8];
            *(float4*)&bb[4] = *(const float4*)&vs[s][eg * 8 + 4];
            #pragma unroll
            for (int i = 0; i < 4; i++)
                #pragma unroll
                for (int j = 0; j < 8; j++) acc[i][j] += a[i] * bb[j];
        }
        if (tid < FDIM) {
            #pragma unroll 8
            for (int s = 0; s < 32; s++) ksacc += ks[s][tid];
        }
        __syncthreads();
    }

    float* dst = g_kvpart + ((size_t)blockIdx.x * BHEADS + bh) * FDIM * HDIM;
    #pragma unroll
    for (int i = 0; i < 4; i++)
        #pragma unroll
        for (int j = 0; j < 8; j++)
            dst[(fg * 4 + i) * HDIM + eg * 8 + j] = acc[i][j];
    if (tid < FDIM)
        g_kspart[(blockIdx.x * BHEADS + bh) * FDIM + tid] = ksacc;
}

__global__ void __launch_bounds__(256)
kv_reduce_kernel()
{
    int i = blockIdx.x * 256 + threadIdx.x;
    float s = 0.f;
    #pragma unroll
    for (int c = 0; c < KVCH; c++) s += g_kvpart[(size_t)c * KVELEM + i];
    g_kv[i] = s;
}

__global__ void __launch_bounds__(256)
ksum_reduce_kernel()
{
    int i = blockIdx.x * 256 + threadIdx.x;   // 0..BHEADS*FDIM-1
    float s = 0.f;
    #pragma unroll
    for (int c = 0; c < KVCH; c++) s += g_kspart[c * BHEADS * FDIM + i];
    g_ksum[i] = s;
}

// ===========================================================================
// qkv + normalize -> bf16 hi/lo planes (input to O projection)
// ===========================================================================
__global__ void __launch_bounds__(256)
qkv_kernel()
{
    __shared__ float kvs[FDIM][HDIM];
    __shared__ float qs[32][FDIM];
    __shared__ float kss[FDIM];

    const int tid = threadIdx.x;
    const int h   = blockIdx.y;
    const int bs0 = blockIdx.x * 32;
    const int b   = bs0 / SEQ;
    const int bh  = b * NHEADS + h;

    #pragma unroll
    for (int i = 0; i < 8; i++) {
        int idx = tid + 256 * i;
        int fr  = idx >> 5;
        int c4  = (idx & 31) * 4;
        *(float4*)&kvs[fr][c4] = *(const float4*)(
            g_kv + (size_t)bh * FDIM * HDIM + fr * HDIM + c4);
    }
    if (tid < FDIM) kss[tid] = g_ksum[bh * FDIM + tid];
    #pragma unroll
    for (int i = 0; i < 2; i++) {
        int idx = tid + 256 * i;
        int sr  = idx >> 4;
        int c4  = (idx & 15) * 4;
        *(float4*)&qs[sr][c4] = *(const float4*)(
            g_qp + ((size_t)(bs0 + sr) * NHEADS + h) * FDIM + c4);
    }
    __syncthreads();

    const int sl = tid >> 3;
    const int e0 = (tid & 7) * 16;

    float den = 0.f;
    #pragma unroll 8
    for (int f = 0; f < FDIM; f++) den += qs[sl][f] * kss[f];
    const float inv = 1.0f / (den + 1e-8f);

    float o[16];
    #pragma unroll
    for (int j = 0; j < 16; j++) o[j] = 0.f;
    #pragma unroll 4
    for (int f = 0; f < FDIM; f++) {
        float q = qs[sl][f];
        const float4* kr = (const float4*)&kvs[f][e0];
        #pragma unroll
        for (int j4 = 0; j4 < 4; j4++) {
            float4 kvv = kr[j4];
            o[j4 * 4 + 0] += q * kvv.x;
            o[j4 * 4 + 1] += q * kvv.y;
            o[j4 * 4 + 2] += q * kvv.z;
            o[j4 * 4 + 3] += q * kvv.w;
        }
    }

    uint32_t H[8], L[8];
    #pragma unroll
    for (int p = 0; p < 8; p++)
        split_pack(o[2 * p] * inv, o[2 * p + 1] * inv, H[p], L[p]);
    size_t didx = (size_t)(bs0 + sl) * HID + h * HDIM + e0;
    *(uint4*)&g_ah[didx]     = make_uint4(H[0], H[1], H[2], H[3]);
    *(uint4*)&g_ah[didx + 8] = make_uint4(H[4], H[5], H[6], H[7]);
    *(uint4*)&g_al[didx]     = make_uint4(L[0], L[1], L[2], L[3]);
    *(uint4*)&g_al[didx + 8] = make_uint4(L[4], L[5], L[6], L[7]);
}

// ===========================================================================
extern "C" void kernel_launch(void* const* d_in, const int* in_sizes, int n_in,
                              void* d_out, int out_size)
{
    const float* query = (const float*)d_in[0];
    const float* key_  = (const float*)d_in[1];
    const float* value = (const float*)d_in[2];
    const float* mask  = (const float*)d_in[3];
    const float* Wq    = (const float*)d_in[4];
    const float* bq    = (const float*)d_in[5];
    const float* Wk    = (const float*)d_in[6];
    const float* bk    = (const float*)d_in[7];
    const float* Wv    = (const float*)d_in[8];
    const float* bv    = (const float*)d_in[9];
    const float* Wqf   = (const float*)d_in[10];
    const float* Wkf   = (const float*)d_in[11];
    const float* Wo    = (const float*)d_in[12];
    const float* bo    = (const float*)d_in[13];
    float* out = (float*)d_out;

    cudaFuncSetAttribute(gemm_tc, cudaFuncAttributeMaxDynamicSharedMemorySize, GSMEM);

    const int nbig = (MROWS * HID) / 8;      // 4194304
    const int nw   = (HID * HID) / 8;        // 524288

    // Launch order puts the q' gemm at index 3 so ncu's fixed-skip capture
    // lands on a gemm_tc instance this round.
    comb_kernel<<<dim3(HID / 128, NHEADS, 2), 256>>>(Wq, Wqf, Wk, Wkf);     // 0
    bias_comb_kernel<<<dim3(NHEADS, 2), 64>>>(bq, Wqf, bk, Wkf);            // 1
    conv_kernel<<<(nbig + 255) / 256, 256>>>(query, 0, nbig);               // 2
    // q' = relu(query @ Wqc^T + bqc) -> g_qp
    gemm_tc<<<dim3(NQP / 128, MROWS / 256), 512, GSMEM>>>(                  // 3
        0, 0, nullptr, 0, nullptr, 0, mask, 1, NQP);
    conv_kernel<<<(nbig + 255) / 256, 256>>>(key_,  1, nbig);               // 4
    // k' = relu(key @ Wkc^T + bkc) * mask -> g_kp
    gemm_tc<<<dim3(NQP / 128, MROWS / 256), 512, GSMEM>>>(                  // 5
        1, 1, nullptr, 1, nullptr, 1, mask, 3, NQP);
    conv_kernel<<<(nbig + 255) / 256, 256>>>(value, 2, nbig);               // 6
    conv_kernel<<<(nw + 255) / 256, 256>>>(Wv, 3, nw);                      // 7
    // V = value @ Wv^T + bv -> g_V
    gemm_tc<<<dim3(HID / 128, MROWS / 256), 512, GSMEM>>>(                  // 8
        2, 2, bv, 2, nullptr, 2, mask, 0, HID);
    conv_kernel<<<(nw + 255) / 256, 256>>>(Wo, 4, nw);                      // 9

    kv_partial_kernel<<<dim3(KVCH, BHEADS), 256>>>();                       // 10
    kv_reduce_kernel<<<KVELEM / 256, 256>>>();                              // 11
    ksum_reduce_kernel<<<(BHEADS * FDIM) / 256, 256>>>();                   // 12
    qkv_kernel<<<dim3(MROWS / 32, NHEADS), 256>>>();                        // 13

    // out = attn @ Wo^T + bo
    gemm_tc<<<dim3(HID / 128, MROWS / 256), 512, GSMEM>>>(                  // 14
        3, 3, bo, 2, out, 3, mask, 0, HID);
}

// round 8
// speedup vs baseline: 1.0514x; 1.0514x over previous
#include <cuda_runtime.h>
#include <cuda_bf16.h>
#include <cstdint>

// Problem constants (fixed by the dataset)
#define BATCH   4
#define SEQ     4096
#define HID     2048
#define NHEADS  16
#define HDIM    128
#define FDIM    64
#define MROWS   (BATCH * SEQ)          // 16384
#define M2      (MROWS * NHEADS)       // 262144
#define BHEADS  (BATCH * NHEADS)       // 64
#define KVCH    16
#define KVELEM  (BHEADS * FDIM * HDIM) // 524288
#define NQP     (NHEADS * FDIM)        // 1024

// ---------------- scratch (static device globals; no allocation) -----------
__device__ float g_V[(size_t)MROWS * HID];
__device__ float g_qp[(size_t)M2 * FDIM];
__device__ float g_kp[(size_t)M2 * FDIM];
__device__ float g_kvpart[(size_t)KVCH * KVELEM];
__device__ float g_kv[KVELEM];
__device__ float g_kspart[KVCH * BHEADS * FDIM];
__device__ float g_ksum[BHEADS * FDIM];
__device__ float g_bqc[NQP];
__device__ float g_bkc[NQP];
// bf16 hi/lo planes
__device__ __nv_bfloat16 g_qh[(size_t)MROWS * HID],  g_ql[(size_t)MROWS * HID];
__device__ __nv_bfloat16 g_kh[(size_t)MROWS * HID],  g_kl[(size_t)MROWS * HID];
__device__ __nv_bfloat16 g_vh[(size_t)MROWS * HID],  g_vl[(size_t)MROWS * HID];
__device__ __nv_bfloat16 g_ah[(size_t)MROWS * HID],  g_al[(size_t)MROWS * HID];
__device__ __nv_bfloat16 g_Wvh[(size_t)HID * HID],   g_Wvl[(size_t)HID * HID];
__device__ __nv_bfloat16 g_Woh[(size_t)HID * HID],   g_Wol[(size_t)HID * HID];
__device__ __nv_bfloat16 g_Wqch[(size_t)NQP * HID],  g_Wqcl[(size_t)NQP * HID];
__device__ __nv_bfloat16 g_Wkch[(size_t)NQP * HID],  g_Wkcl[(size_t)NQP * HID];

// =========================== helpers =======================================
__device__ __forceinline__ uint32_t smem_u32(const void* p) {
    uint32_t a;
    asm("{ .reg .u64 t; cvta.to.shared.u64 t, %1; cvt.u32.u64 %0, t; }"
        : "=r"(a) : "l"(p));
    return a;
}
#define SMEM_SWIZZLE_128B(off) ((off) ^ (((off) >> 3) & 0x70))

__device__ __forceinline__ void cp16(uint32_t dst, const void* src) {
    asm volatile("cp.async.cg.shared.global [%0], [%1], 16;"
                 :: "r"(dst), "l"(src) : "memory");
}
#define CP_COMMIT() asm volatile("cp.async.commit_group;" ::: "memory")
#define CP_WAIT1()  asm volatile("cp.async.wait_group 1;" ::: "memory")

__device__ __forceinline__ void ldsm_x4(uint32_t& r0, uint32_t& r1,
                                        uint32_t& r2, uint32_t& r3,
                                        uint32_t addr) {
    asm volatile("ldmatrix.sync.aligned.m8n8.x4.shared.b16 {%0,%1,%2,%3}, [%4];"
                 : "=r"(r0), "=r"(r1), "=r"(r2), "=r"(r3) : "r"(addr));
}
__device__ __forceinline__ void mma_bf16(float* d, const uint32_t* a,
                                         const uint32_t* b) {
    asm volatile(
        "mma.sync.aligned.m16n8k16.row.col.f32.bf16.bf16.f32 "
        "{%0,%1,%2,%3}, {%4,%5,%6,%7}, {%8,%9}, {%0,%1,%2,%3};"
        : "+f"(d[0]), "+f"(d[1]), "+f"(d[2]), "+f"(d[3])
        : "r"(a[0]), "r"(a[1]), "r"(a[2]), "r"(a[3]), "r"(b[0]), "r"(b[1]));
}
__device__ __forceinline__ void split_pack(float x, float y, uint32_t& h, uint32_t& l) {
    __nv_bfloat16 hx = __float2bfloat16(x);
    __nv_bfloat16 hy = __float2bfloat16(y);
    h = (uint32_t)__bfloat16_as_ushort(hx) |
        ((uint32_t)__bfloat16_as_ushort(hy) << 16);
    __nv_bfloat16 lx = __float2bfloat16(x - __bfloat162float(hx));
    __nv_bfloat16 ly = __float2bfloat16(y - __bfloat162float(hy));
    l = (uint32_t)__bfloat16_as_ushort(lx) |
        ((uint32_t)__bfloat16_as_ushort(ly) << 16);
}

// ===========================================================================
// fp32 -> bf16 hi/lo plane conversion
// ===========================================================================
__global__ void __launch_bounds__(256)
conv3_kernel(const float* __restrict__ q, const float* __restrict__ k,
             const float* __restrict__ v, int n8)
{
    const int sel = blockIdx.y;
    const float* src = (sel == 0) ? q : (sel == 1) ? k : v;
    __nv_bfloat16* dh = (sel == 0) ? g_qh : (sel == 1) ? g_kh : g_vh;
    __nv_bfloat16* dl = (sel == 0) ? g_ql : (sel == 1) ? g_kl : g_vl;
    int i = blockIdx.x * 256 + threadIdx.x;
    if (i >= n8) return;
    const float4* s4 = (const float4*)src + (size_t)i * 2;
    float4 v0 = s4[0], v1 = s4[1];
    uint32_t h[4], l[4];
    split_pack(v0.x, v0.y, h[0], l[0]);
    split_pack(v0.z, v0.w, h[1], l[1]);
    split_pack(v1.x, v1.y, h[2], l[2]);
    split_pack(v1.z, v1.w, h[3], l[3]);
    *(uint4*)(dh + (size_t)i * 8) = make_uint4(h[0], h[1], h[2], h[3]);
    *(uint4*)(dl + (size_t)i * 8) = make_uint4(l[0], l[1], l[2], l[3]);
}

__global__ void __launch_bounds__(256)
convw_kernel(const float* __restrict__ src, int sel, int n8)
{
    __nv_bfloat16* dh = sel ? g_Woh : g_Wvh;
    __nv_bfloat16* dl = sel ? g_Wol : g_Wvl;
    int i = blockIdx.x * 256 + threadIdx.x;
    if (i >= n8) return;
    const float4* s4 = (const float4*)src + (size_t)i * 2;
    float4 v0 = s4[0], v1 = s4[1];
    uint32_t h[4], l[4];
    split_pack(v0.x, v0.y, h[0], l[0]);
    split_pack(v0.z, v0.w, h[1], l[1]);
    split_pack(v1.x, v1.y, h[2], l[2]);
    split_pack(v1.z, v1.w, h[3], l[3]);
    *(uint4*)(dh + (size_t)i * 8) = make_uint4(h[0], h[1], h[2], h[3]);
    *(uint4*)(dl + (size_t)i * 8) = make_uint4(l[0], l[1], l[2], l[3]);
}

// ===========================================================================
// Tensor-core GEMM, bf16 3-term split, cp.async double-buffered, 2 CTA/SM.
// 128x128 tile, TILE_K=32, hi|lo packed in one 128B row (SW128).
// mode 0: merged q'/k'/V GEMMs (grid 4096); mode 1: O GEMM (grid 2048).
// ===========================================================================
#define TILE_K   32
#define CHUNKS   (HID / TILE_K)   // 64
#define OFF_A    0
#define OFF_B    16384
#define STG      32768            // A 16KB + B 16KB per stage
#define GSMEM    (2 * STG)        // 65536

__device__ __forceinline__ void stage_load(
    uint32_t sbuf, const __nv_bfloat16* pa, const __nv_bfloat16* pb,
    uint32_t cb, int r0)
{
    // pa/pb pre-offset: plane base (+k0 + (q&3)*8). cb = q*16 byte col.
    #pragma unroll
    for (int i = 0; i < 4; i++) {
        int r = r0 + i * 32;
        uint32_t off = SMEM_SWIZZLE_128B((uint32_t)(r * 128) + cb);
        cp16(sbuf + OFF_A + off, pa + (size_t)r * HID);
        cp16(sbuf + OFF_B + off, pb + (size_t)r * HID);
    }
}

__global__ void __launch_bounds__(256, 2)
gemm_tc(int mode, const float* __restrict__ bvv, const float* __restrict__ boo,
        float* __restrict__ outp, const float* __restrict__ mask)
{
    extern __shared__ char smem[];

    // ---- block decode ----
    int op, bx, by;
    if (mode == 0) {
        int b = blockIdx.x;
        if (b < 1024)      { op = 0; bx = b & 7; by = b >> 3; }
        else if (b < 2048) { b -= 1024; op = 1; bx = b & 7; by = b >> 3; }
        else               { b -= 2048; op = 2; bx = b & 15; by = b >> 4; }
    } else {
        int b = blockIdx.x;  op = 3; bx = b & 15; by = b >> 4;
    }
    const __nv_bfloat16 *Ah, *Al, *Wh, *Wl;
    const float* bias;
    float* C;
    int N, flags;
    switch (op) {
        case 0: Ah = g_qh; Al = g_ql; Wh = g_Wqch; Wl = g_Wqcl;
                bias = g_bqc; C = g_qp; N = NQP; flags = 1; break;
        case 1: Ah = g_kh; Al = g_kl; Wh = g_Wkch; Wl = g_Wkcl;
                bias = g_bkc; C = g_kp; N = NQP; flags = 3; break;
        case 2: Ah = g_vh; Al = g_vl; Wh = g_Wvh; Wl = g_Wvl;
                bias = bvv; C = g_V; N = HID; flags = 0; break;
        default: Ah = g_ah; Al = g_al; Wh = g_Woh; Wl = g_Wol;
                bias = boo; C = outp; N = HID; flags = 0; break;
    }
    const int bn = bx * 128;
    const int bm = by * 128;

    const uint32_t sb = smem_u32(smem);
    const int tid  = threadIdx.x;
    const int lane = tid & 31;
    const int wid  = tid >> 5;
    const int wm   = wid >> 2;         // 0..1  (M: 2 x 64)
    const int wn   = wid & 3;          // 0..3  (N: 4 x 32)

    // staging per-thread constants: q = col chunk 0..7 (0-3 hi, 4-7 lo)
    const int q_ = tid & 7;
    const int r0_ = tid >> 3;          // 0..31
    const uint32_t cb_ = (uint32_t)(q_ * 16);
    const int eoff = (q_ & 3) * 8;
    const __nv_bfloat16* Abase = ((q_ < 4) ? Ah : Al) + (size_t)bm * HID + eoff;
    const __nv_bfloat16* Bbase = ((q_ < 4) ? Wh : Wl) + (size_t)bn * HID + eoff;

    const uint32_t a_row  = (uint32_t)(wm * 64 + (lane & 15));
    const uint32_t a_kofs = (uint32_t)((lane >> 4) * 16);
    const uint32_t b_row  = (uint32_t)(wn * 32 + (lane & 7) + ((lane & 16) >> 1));
    const uint32_t b_kofs = (uint32_t)((lane & 8) * 2);

    float acc[4][4][4];
    #pragma unroll
    for (int mf = 0; mf < 4; mf++)
        #pragma unroll
        for (int nf = 0; nf < 4; nf++)
            #pragma unroll
            for (int j = 0; j < 4; j++) acc[mf][nf][j] = 0.f;

    // prologue
    stage_load(sb + 0 * STG, Abase, Bbase, cb_, r0_);
    CP_COMMIT();
    stage_load(sb + 1 * STG, Abase + TILE_K, Bbase + TILE_K, cb_, r0_);
    CP_COMMIT();

    #pragma unroll 1
    for (int c = 0; c < CHUNKS; c++) {
        CP_WAIT1();
        __syncthreads();

        const uint32_t sbase = sb + (c & 1) * STG;
        #pragma unroll
        for (int ks = 0; ks < 2; ks++) {
            const uint32_t kb = (uint32_t)(ks * 32);
            uint32_t bhf[8], blf[8];
            #pragma unroll
            for (int nf2 = 0; nf2 < 2; nf2++) {
                uint32_t off = SMEM_SWIZZLE_128B(
                    (b_row + nf2 * 16) * 128 + kb + b_kofs);
                ldsm_x4(bhf[nf2*4+0], bhf[nf2*4+1], bhf[nf2*4+2], bhf[nf2*4+3],
                        sbase + OFF_B + off);
                ldsm_x4(blf[nf2*4+0], blf[nf2*4+1], blf[nf2*4+2], blf[nf2*4+3],
                        sbase + OFF_B + (off ^ 64u));
            }
            #pragma unroll
            for (int mf = 0; mf < 4; mf++) {
                uint32_t aoff = SMEM_SWIZZLE_128B(
                    (a_row + mf * 16) * 128 + kb + a_kofs);
                uint32_t ah[4], al[4];
                ldsm_x4(ah[0], ah[1], ah[2], ah[3], sbase + OFF_A + aoff);
                ldsm_x4(al[0], al[1], al[2], al[3], sbase + OFF_A + (aoff ^ 64u));
                #pragma unroll
                for (int nf = 0; nf < 4; nf++) {
                    mma_bf16(acc[mf][nf], ah, &bhf[nf * 2]);   // hi*hi
                    mma_bf16(acc[mf][nf], ah, &blf[nf * 2]);   // hi*lo
                    mma_bf16(acc[mf][nf], al, &bhf[nf * 2]);   // lo*hi
                }
            }
        }

        __syncthreads();       // all reads of stage c done
        if (c + 2 < CHUNKS)
            stage_load(sb + (c & 1) * STG, Abase + (c + 2) * TILE_K,
                       Bbase + (c + 2) * TILE_K, cb_, r0_);
        CP_COMMIT();           // empty commits are legal no-ops
    }

    // ---- epilogue: bias [+relu][+mask] ----
    const int tq = lane >> 2;
    const int tr = lane & 3;
    float2 bv[4];
    #pragma unroll
    for (int nf = 0; nf < 4; nf++) {
        int col = bn + wn * 32 + nf * 8 + tr * 2;
        bv[nf].x = bias[col];
        bv[nf].y = bias[col + 1];
    }
    #pragma unroll
    for (int mf = 0; mf < 4; mf++) {
        #pragma unroll
        for (int half = 0; half < 2; half++) {
            int row = bm + wm * 64 + mf * 16 + tq + half * 8;
            float mv = (flags & 2) ? mask[row] : 1.0f;
            float* dst = C + (size_t)row * N + bn + wn * 32 + tr * 2;
            #pragma unroll
            for (int nf = 0; nf < 4; nf++) {
                float2 v;
                v.x = acc[mf][nf][half * 2 + 0] + bv[nf].x;
                v.y = acc[mf][nf][half * 2 + 1] + bv[nf].y;
                if (flags & 1) { v.x = fmaxf(v.x, 0.f); v.y = fmaxf(v.y, 0.f); }
                v.x *= mv; v.y *= mv;
                *(float2*)(dst + nf * 8) = v;
            }
        }
    }
}

// ===========================================================================
// Combined-weight precompute -> bf16 hi/lo planes (+ combined bias)
// ===========================================================================
__global__ void __launch_bounds__(256)
comb_kernel(const float* __restrict__ Wq, const float* __restrict__ Wqf,
            const float* __restrict__ Wk, const float* __restrict__ Wkf,
            const float* __restrict__ bq, const float* __restrict__ bk)
{
    const int isk = blockIdx.z;
    const float* Wbig = isk ? Wk : Wq;
    const float* Wf   = isk ? Wkf : Wqf;
    __nv_bfloat16* outh = isk ? g_Wkch : g_Wqch;
    __nv_bfloat16* outl = isk ? g_Wkcl : g_Wqcl;
    const int h  = blockIdx.y;
    const int e0 = blockIdx.x * 128;

    __shared__ float Wfs[FDIM][HDIM + 1];
    __shared__ float Ws[16][128];

    const int tid = threadIdx.x;
    for (int idx = tid; idx < FDIM * HDIM; idx += 256)
        Wfs[idx >> 7][idx & 127] = Wf[idx];
    __syncthreads();

    // combined bias (once per (isk,h))
    if (blockIdx.x == 0 && tid < FDIM) {
        const float* b = isk ? bk : bq;
        float s = 0.f;
        for (int d = 0; d < HDIM; d++) s += Wfs[tid][d] * b[h * HDIM + d];
        (isk ? g_bkc : g_bqc)[h * FDIM + tid] = s;
    }

    const int f  = tid & 63;
    const int eg = tid >> 6;
    float acc[32];
    #pragma unroll
    for (int j = 0; j < 32; j++) acc[j] = 0.f;

    for (int d0 = 0; d0 < HDIM; d0 += 16) {
        __syncthreads();
        #pragma unroll
        for (int i = 0; i < 2; i++) {
            int idx = tid + 256 * i;
            int dd  = idx >> 5;
            int c4  = (idx & 31) * 4;
            *(float4*)&Ws[dd][c4] =
                *(const float4*)(Wbig + (size_t)(h * HDIM + d0 + dd) * HID + e0 + c4);
        }
        __syncthreads();
        #pragma unroll
        for (int dd = 0; dd < 16; dd++) {
            float wf = Wfs[f][d0 + dd];
            #pragma unroll
            for (int j = 0; j < 32; j++)
                acc[j] += wf * Ws[dd][eg * 32 + j];
        }
    }
    #pragma unroll
    for (int j = 0; j < 32; j++) {
        size_t idx = (size_t)(h * FDIM + f) * HID + e0 + eg * 32 + j;
        float v = acc[j];
        __nv_bfloat16 hb = __float2bfloat16(v);
        outh[idx] = hb;
        outl[idx] = __float2bfloat16(v - __bfloat162float(hb));
    }
}

// ===========================================================================
// kv partial + per-chunk k' column sums (deterministic split-K)
// ===========================================================================
__global__ void __launch_bounds__(256)
kv_partial_kernel()
{
    __shared__ float ks[32][FDIM];
    __shared__ float vs[32][HDIM];

    const int tid = threadIdx.x;
    const int bh  = blockIdx.y;
    const int b   = bh >> 4, h = bh & 15;
    const int s0  = blockIdx.x * (SEQ / KVCH);
    const int fg  = tid >> 4;
    const int eg  = tid & 15;

    float acc[4][8];
    #pragma unroll
    for (int i = 0; i < 4; i++)
        #pragma unroll
        for (int j = 0; j < 8; j++) acc[i][j] = 0.f;
    float ksacc = 0.f;

    for (int ss = 0; ss < SEQ / KVCH; ss += 32) {
        #pragma unroll
        for (int i = 0; i < 2; i++) {
            int idx = tid + 256 * i;
            int sr  = idx >> 4;
            int c4  = (idx & 15) * 4;
            *(float4*)&ks[sr][c4] = *(const float4*)(
                g_kp + ((size_t)(b * SEQ + s0 + ss + sr) * NHEADS + h) * FDIM + c4);
        }
        #pragma unroll
        for (int i = 0; i < 4; i++) {
            int idx = tid + 256 * i;
            int sr  = idx >> 5;
            int c4  = (idx & 31) * 4;
            *(float4*)&vs[sr][c4] = *(const float4*)(
                g_V + (size_t)(b * SEQ + s0 + ss + sr) * HID + h * HDIM + c4);
        }
        __syncthreads();

        #pragma unroll 4
        for (int s = 0; s < 32; s++) {
            float a[4];
            *(float4*)a = *(const float4*)&ks[s][fg * 4];
            float bb[8];
            *(float4*)&bb[0] = *(const float4*)&vs[s][eg * 8];
            *(float4*)&bb[4] = *(const float4*)&vs[s][eg * 8 + 4];
            #pragma unroll
            for (int i = 0; i < 4; i++)
                #pragma unroll
                for (int j = 0; j < 8; j++) acc[i][j] += a[i] * bb[j];
        }
        if (tid < FDIM) {
            #pragma unroll 8
            for (int s = 0; s < 32; s++) ksacc += ks[s][tid];
        }
        __syncthreads();
    }

    float* dst = g_kvpart + ((size_t)blockIdx.x * BHEADS + bh) * FDIM * HDIM;
    #pragma unroll
    for (int i = 0; i < 4; i++)
        #pragma unroll
        for (int j = 0; j < 8; j++)
            dst[(fg * 4 + i) * HDIM + eg * 8 + j] = acc[i][j];
    if (tid < FDIM)
        g_kspart[(blockIdx.x * BHEADS + bh) * FDIM + tid] = ksacc;
}

__global__ void __launch_bounds__(256)
kv_reduce_kernel()
{
    int i = blockIdx.x * 256 + threadIdx.x;
    float s = 0.f;
    #pragma unroll
    for (int c = 0; c < KVCH; c++) s += g_kvpart[(size_t)c * KVELEM + i];
    g_kv[i] = s;
}

__global__ void __launch_bounds__(256)
ksum_reduce_kernel()
{
    int i = blockIdx.x * 256 + threadIdx.x;
    float s = 0.f;
    #pragma unroll
    for (int c = 0; c < KVCH; c++) s += g_kspart[c * BHEADS * FDIM + i];
    g_ksum[i] = s;
}

// ===========================================================================
// qkv + normalize -> bf16 hi/lo planes (input to O projection)
// ===========================================================================
__global__ void __launch_bounds__(256)
qkv_kernel()
{
    __shared__ float kvs[FDIM][HDIM];
    __shared__ float qs[32][FDIM];
    __shared__ float kss[FDIM];

    const int tid = threadIdx.x;
    const int h   = blockIdx.y;
    const int bs0 = blockIdx.x * 32;
    const int b   = bs0 / SEQ;
    const int bh  = b * NHEADS + h;

    #pragma unroll
    for (int i = 0; i < 8; i++) {
        int idx = tid + 256 * i;
        int fr  = idx >> 5;
        int c4  = (idx & 31) * 4;
        *(float4*)&kvs[fr][c4] = *(const float4*)(
            g_kv + (size_t)bh * FDIM * HDIM + fr * HDIM + c4);
    }
    if (tid < FDIM) kss[tid] = g_ksum[bh * FDIM + tid];
    #pragma unroll
    for (int i = 0; i < 2; i++) {
        int idx = tid + 256 * i;
        int sr  = idx >> 4;
        int c4  = (idx & 15) * 4;
        *(float4*)&qs[sr][c4] = *(const float4*)(
            g_qp + ((size_t)(bs0 + sr) * NHEADS + h) * FDIM + c4);
    }
    __syncthreads();

    const int sl = tid >> 3;
    const int e0 = (tid & 7) * 16;

    float den = 0.f;
    #pragma unroll 8
    for (int f = 0; f < FDIM; f++) den += qs[sl][f] * kss[f];
    const float inv = 1.0f / (den + 1e-8f);

    float o[16];
    #pragma unroll
    for (int j = 0; j < 16; j++) o[j] = 0.f;
    #pragma unroll 4
    for (int f = 0; f < FDIM; f++) {
        float q = qs[sl][f];
        const float4* kr = (const float4*)&kvs[f][e0];
        #pragma unroll
        for (int j4 = 0; j4 < 4; j4++) {
            float4 kvv = kr[j4];
            o[j4 * 4 + 0] += q * kvv.x;
            o[j4 * 4 + 1] += q * kvv.y;
            o[j4 * 4 + 2] += q * kvv.z;
            o[j4 * 4 + 3] += q * kvv.w;
        }
    }

    uint32_t H[8], L[8];
    #pragma unroll
    for (int p = 0; p < 8; p++)
        split_pack(o[2 * p] * inv, o[2 * p + 1] * inv, H[p], L[p]);
    size_t didx = (size_t)(bs0 + sl) * HID + h * HDIM + e0;
    *(uint4*)&g_ah[didx]     = make_uint4(H[0], H[1], H[2], H[3]);
    *(uint4*)&g_ah[didx + 8] = make_uint4(H[4], H[5], H[6], H[7]);
    *(uint4*)&g_al[didx]     = make_uint4(L[0], L[1], L[2], L[3]);
    *(uint4*)&g_al[didx + 8] = make_uint4(L[4], L[5], L[6], L[7]);
}

// ===========================================================================
extern "C" void kernel_launch(void* const* d_in, const int* in_sizes, int n_in,
                              void* d_out, int out_size)
{
    const float* query = (const float*)d_in[0];
    const float* key_  = (const float*)d_in[1];
    const float* value = (const float*)d_in[2];
    const float* mask  = (const float*)d_in[3];
    const float* Wq    = (const float*)d_in[4];
    const float* bq    = (const float*)d_in[5];
    const float* Wk    = (const float*)d_in[6];
    const float* bk    = (const float*)d_in[7];
    const float* Wv    = (const float*)d_in[8];
    const float* bv    = (const float*)d_in[9];
    const float* Wqf   = (const float*)d_in[10];
    const float* Wkf   = (const float*)d_in[11];
    const float* Wo    = (const float*)d_in[12];
    const float* bo    = (const float*)d_in[13];
    float* out = (float*)d_out;

    cudaFuncSetAttribute(gemm_tc, cudaFuncAttributeMaxDynamicSharedMemorySize, GSMEM);

    const int nbig = (MROWS * HID) / 8;      // 4194304
    const int nw   = (HID * HID) / 8;        // 524288

    comb_kernel<<<dim3(HID / 128, NHEADS, 2), 256>>>(Wq, Wqf, Wk, Wkf, bq, bk); // 0
    conv3_kernel<<<dim3((nbig + 255) / 256, 3), 256>>>(query, key_, value, nbig); // 1
    convw_kernel<<<(nw + 255) / 256, 256>>>(Wv, 0, nw);                          // 2
    // merged q' / k' / V GEMMs
    gemm_tc<<<4096, 256, GSMEM>>>(0, bv, nullptr, nullptr, mask);                // 3
    convw_kernel<<<(nw + 255) / 256, 256>>>(Wo, 1, nw);                          // 4

    kv_partial_kernel<<<dim3(KVCH, BHEADS), 256>>>();                            // 5
    kv_reduce_kernel<<<KVELEM / 256, 256>>>();                                   // 6
    ksum_reduce_kernel<<<(BHEADS * FDIM) / 256, 256>>>();                        // 7
    qkv_kernel<<<dim3(MROWS / 32, NHEADS), 256>>>();                             // 8

    // out = attn @ Wo^T + bo
    gemm_tc<<<2048, 256, GSMEM>>>(1, nullptr, bo, out, mask);                    // 9
}

// round 9
// speedup vs baseline: 1.1651x; 1.1082x over previous
#include <cuda_runtime.h>
#include <cuda_bf16.h>
#include <cstdint>

// Problem constants (fixed by the dataset)
#define BATCH   4
#define SEQ     4096
#define HID     2048
#define NHEADS  16
#define HDIM    128
#define FDIM    64
#define MROWS   (BATCH * SEQ)          // 16384
#define M2      (MROWS * NHEADS)       // 262144
#define BHEADS  (BATCH * NHEADS)       // 64
#define KVCH    16
#define KVELEM  (BHEADS * FDIM * HDIM) // 524288
#define NQP     (NHEADS * FDIM)        // 1024

// ---------------- scratch (static device globals; no allocation) -----------
__device__ float g_V[(size_t)MROWS * HID];
__device__ float g_qp[(size_t)M2 * FDIM];
__device__ float g_kp[(size_t)M2 * FDIM];
__device__ float g_kvpart[(size_t)KVCH * KVELEM];
__device__ float g_kv[KVELEM];
__device__ float g_kspart[KVCH * BHEADS * FDIM];
__device__ float g_ksum[BHEADS * FDIM];
__device__ float g_bqc[NQP];
__device__ float g_bkc[NQP];
// bf16 hi/lo planes
__device__ __nv_bfloat16 g_qh[(size_t)MROWS * HID],  g_ql[(size_t)MROWS * HID];
__device__ __nv_bfloat16 g_kh[(size_t)MROWS * HID],  g_kl[(size_t)MROWS * HID];
__device__ __nv_bfloat16 g_vh[(size_t)MROWS * HID],  g_vl[(size_t)MROWS * HID];
__device__ __nv_bfloat16 g_ah[(size_t)MROWS * HID],  g_al[(size_t)MROWS * HID];
__device__ __nv_bfloat16 g_Wvh[(size_t)HID * HID],   g_Wvl[(size_t)HID * HID];
__device__ __nv_bfloat16 g_Woh[(size_t)HID * HID],   g_Wol[(size_t)HID * HID];
__device__ __nv_bfloat16 g_Wqch[(size_t)NQP * HID],  g_Wqcl[(size_t)NQP * HID];
__device__ __nv_bfloat16 g_Wkch[(size_t)NQP * HID],  g_Wkcl[(size_t)NQP * HID];

// =========================== helpers =======================================
__device__ __forceinline__ uint32_t smem_u32(const void* p) {
    uint32_t a;
    asm("{ .reg .u64 t; cvta.to.shared.u64 t, %1; cvt.u32.u64 %0, t; }"
        : "=r"(a) : "l"(p));
    return a;
}
#define SMEM_SWIZZLE_128B(off) ((off) ^ (((off) >> 3) & 0x70))

__device__ __forceinline__ void cp16(uint32_t dst, const void* src) {
    asm volatile("cp.async.cg.shared.global [%0], [%1], 16;"
                 :: "r"(dst), "l"(src) : "memory");
}
#define CP_COMMIT() asm volatile("cp.async.commit_group;" ::: "memory")
#define CP_WAIT1()  asm volatile("cp.async.wait_group 1;" ::: "memory")

__device__ __forceinline__ void ldsm_x4(uint32_t& r0, uint32_t& r1,
                                        uint32_t& r2, uint32_t& r3,
                                        uint32_t addr) {
    asm volatile("ldmatrix.sync.aligned.m8n8.x4.shared.b16 {%0,%1,%2,%3}, [%4];"
                 : "=r"(r0), "=r"(r1), "=r"(r2), "=r"(r3) : "r"(addr));
}
__device__ __forceinline__ void mma_bf16(float* d, const uint32_t* a,
                                         const uint32_t* b) {
    asm volatile(
        "mma.sync.aligned.m16n8k16.row.col.f32.bf16.bf16.f32 "
        "{%0,%1,%2,%3}, {%4,%5,%6,%7}, {%8,%9}, {%0,%1,%2,%3};"
        : "+f"(d[0]), "+f"(d[1]), "+f"(d[2]), "+f"(d[3])
        : "r"(a[0]), "r"(a[1]), "r"(a[2]), "r"(a[3]), "r"(b[0]), "r"(b[1]));
}
__device__ __forceinline__ void split_pack(float x, float y, uint32_t& h, uint32_t& l) {
    __nv_bfloat16 hx = __float2bfloat16(x);
    __nv_bfloat16 hy = __float2bfloat16(y);
    h = (uint32_t)__bfloat16_as_ushort(hx) |
        ((uint32_t)__bfloat16_as_ushort(hy) << 16);
    __nv_bfloat16 lx = __float2bfloat16(x - __bfloat162float(hx));
    __nv_bfloat16 ly = __float2bfloat16(y - __bfloat162float(hy));
    l = (uint32_t)__bfloat16_as_ushort(lx) |
        ((uint32_t)__bfloat16_as_ushort(ly) << 16);
}

// ===========================================================================
// fp32 -> bf16 hi/lo plane conversion
// ===========================================================================
__global__ void __launch_bounds__(256)
conv3_kernel(const float* __restrict__ q, const float* __restrict__ k,
             const float* __restrict__ v, int n8)
{
    const int sel = blockIdx.y;
    const float* src = (sel == 0) ? q : (sel == 1) ? k : v;
    __nv_bfloat16* dh = (sel == 0) ? g_qh : (sel == 1) ? g_kh : g_vh;
    __nv_bfloat16* dl = (sel == 0) ? g_ql : (sel == 1) ? g_kl : g_vl;
    int i = blockIdx.x * 256 + threadIdx.x;
    if (i >= n8) return;
    const float4* s4 = (const float4*)src + (size_t)i * 2;
    float4 v0 = s4[0], v1 = s4[1];
    uint32_t h[4], l[4];
    split_pack(v0.x, v0.y, h[0], l[0]);
    split_pack(v0.z, v0.w, h[1], l[1]);
    split_pack(v1.x, v1.y, h[2], l[2]);
    split_pack(v1.z, v1.w, h[3], l[3]);
    *(uint4*)(dh + (size_t)i * 8) = make_uint4(h[0], h[1], h[2], h[3]);
    *(uint4*)(dl + (size_t)i * 8) = make_uint4(l[0], l[1], l[2], l[3]);
}

__global__ void __launch_bounds__(256)
convw_kernel(const float* __restrict__ src, int sel, int n8)
{
    __nv_bfloat16* dh = sel ? g_Woh : g_Wvh;
    __nv_bfloat16* dl = sel ? g_Wol : g_Wvl;
    int i = blockIdx.x * 256 + threadIdx.x;
    if (i >= n8) return;
    const float4* s4 = (const float4*)src + (size_t)i * 2;
    float4 v0 = s4[0], v1 = s4[1];
    uint32_t h[4], l[4];
    split_pack(v0.x, v0.y, h[0], l[0]);
    split_pack(v0.z, v0.w, h[1], l[1]);
    split_pack(v1.x, v1.y, h[2], l[2]);
    split_pack(v1.z, v1.w, h[3], l[3]);
    *(uint4*)(dh + (size_t)i * 8) = make_uint4(h[0], h[1], h[2], h[3]);
    *(uint4*)(dl + (size_t)i * 8) = make_uint4(l[0], l[1], l[2], l[3]);
}

// ===========================================================================
// Tensor-core GEMM, bf16 3-term split, cp.async 3-stage single-barrier
// pipeline, 2 CTA/SM. 128x128 tile, TILE_K=32, hi|lo packed per 128B row.
// mode 0: merged q'/k'/V GEMMs (grid 4096); mode 1: O GEMM (grid 2048).
// ===========================================================================
#define TILE_K   32
#define CHUNKS   (HID / TILE_K)   // 64
#define OFF_A    0
#define OFF_B    16384
#define STG      32768            // A 16KB + B 16KB per stage
#define NSTAGE   3
#define GSMEM    (NSTAGE * STG)   // 98304

__device__ __forceinline__ void stage_load(
    uint32_t sbuf, const __nv_bfloat16* pa, const __nv_bfloat16* pb,
    uint32_t cb, int r0)
{
    #pragma unroll
    for (int i = 0; i < 4; i++) {
        int r = r0 + i * 32;
        uint32_t off = SMEM_SWIZZLE_128B((uint32_t)(r * 128) + cb);
        cp16(sbuf + OFF_A + off, pa + (size_t)r * HID);
        cp16(sbuf + OFF_B + off, pb + (size_t)r * HID);
    }
}

__global__ void __launch_bounds__(256, 2)
gemm_tc(int mode, const float* __restrict__ bvv, const float* __restrict__ boo,
        float* __restrict__ outp, const float* __restrict__ mask)
{
    extern __shared__ char smem[];

    // ---- block decode ----
    int op, bx, by;
    if (mode == 0) {
        int b = blockIdx.x;
        if (b < 1024)      { op = 0; bx = b & 7; by = b >> 3; }
        else if (b < 2048) { b -= 1024; op = 1; bx = b & 7; by = b >> 3; }
        else               { b -= 2048; op = 2; bx = b & 15; by = b >> 4; }
    } else {
        int b = blockIdx.x;  op = 3; bx = b & 15; by = b >> 4;
    }
    const __nv_bfloat16 *Ah, *Al, *Wh, *Wl;
    const float* bias;
    float* C;
    int N, flags;
    switch (op) {
        case 0: Ah = g_qh; Al = g_ql; Wh = g_Wqch; Wl = g_Wqcl;
                bias = g_bqc; C = g_qp; N = NQP; flags = 1; break;
        case 1: Ah = g_kh; Al = g_kl; Wh = g_Wkch; Wl = g_Wkcl;
                bias = g_bkc; C = g_kp; N = NQP; flags = 3; break;
        case 2: Ah = g_vh; Al = g_vl; Wh = g_Wvh; Wl = g_Wvl;
                bias = bvv; C = g_V; N = HID; flags = 0; break;
        default: Ah = g_ah; Al = g_al; Wh = g_Woh; Wl = g_Wol;
                bias = boo; C = outp; N = HID; flags = 0; break;
    }
    const int bn = bx * 128;
    const int bm = by * 128;

    const uint32_t sb = smem_u32(smem);
    const int tid  = threadIdx.x;
    const int lane = tid & 31;
    const int wid  = tid >> 5;
    const int wm   = wid >> 2;         // 0..1  (M: 2 x 64)
    const int wn   = wid & 3;          // 0..3  (N: 4 x 32)

    // staging per-thread constants: q = col chunk 0..7 (0-3 hi, 4-7 lo)
    const int q_ = tid & 7;
    const int r0_ = tid >> 3;          // 0..31
    const uint32_t cb_ = (uint32_t)(q_ * 16);
    const int eoff = (q_ & 3) * 8;
    const __nv_bfloat16* Abase = ((q_ < 4) ? Ah : Al) + (size_t)bm * HID + eoff;
    const __nv_bfloat16* Bbase = ((q_ < 4) ? Wh : Wl) + (size_t)bn * HID + eoff;

    const uint32_t a_row  = (uint32_t)(wm * 64 + (lane & 15));
    const uint32_t a_kofs = (uint32_t)((lane >> 4) * 16);
    const uint32_t b_row  = (uint32_t)(wn * 32 + (lane & 7) + ((lane & 16) >> 1));
    const uint32_t b_kofs = (uint32_t)((lane & 8) * 2);

    float acc[4][4][4];
    #pragma unroll
    for (int mf = 0; mf < 4; mf++)
        #pragma unroll
        for (int nf = 0; nf < 4; nf++)
            #pragma unroll
            for (int j = 0; j < 4; j++) acc[mf][nf][j] = 0.f;

    // prologue: stages 0,1
    stage_load(sb + 0 * STG, Abase, Bbase, cb_, r0_);
    CP_COMMIT();
    stage_load(sb + 1 * STG, Abase + TILE_K, Bbase + TILE_K, cb_, r0_);
    CP_COMMIT();

    #pragma unroll 1
    for (int c = 0; c < CHUNKS; c++) {
        CP_WAIT1();            // my stage-c loads done (only c+1 may pend)
        __syncthreads();       // => ALL threads' stage-c loads done; also all
                               //    readers of stage c-1 (slot (c+2)%3) passed

        if (c + 2 < CHUNKS)
            stage_load(sb + ((c + 2) % NSTAGE) * STG,
                       Abase + (c + 2) * TILE_K, Bbase + (c + 2) * TILE_K,
                       cb_, r0_);
        CP_COMMIT();           // empty commits are legal no-ops

        const uint32_t sbase = sb + (c % NSTAGE) * STG;
        #pragma unroll
        for (int ks = 0; ks < 2; ks++) {
            const uint32_t kb = (uint32_t)(ks * 32);
            uint32_t bhf[8], blf[8];
            #pragma unroll
            for (int nf2 = 0; nf2 < 2; nf2++) {
                uint32_t off = SMEM_SWIZZLE_128B(
                    (b_row + nf2 * 16) * 128 + kb + b_kofs);
                ldsm_x4(bhf[nf2*4+0], bhf[nf2*4+1], bhf[nf2*4+2], bhf[nf2*4+3],
                        sbase + OFF_B + off);
                ldsm_x4(blf[nf2*4+0], blf[nf2*4+1], blf[nf2*4+2], blf[nf2*4+3],
                        sbase + OFF_B + (off ^ 64u));
            }
            #pragma unroll
            for (int mf = 0; mf < 4; mf++) {
                uint32_t aoff = SMEM_SWIZZLE_128B(
                    (a_row + mf * 16) * 128 + kb + a_kofs);
                uint32_t ah[4], al[4];
                ldsm_x4(ah[0], ah[1], ah[2], ah[3], sbase + OFF_A + aoff);
                ldsm_x4(al[0], al[1], al[2], al[3], sbase + OFF_A + (aoff ^ 64u));
                #pragma unroll
                for (int nf = 0; nf < 4; nf++) {
                    mma_bf16(acc[mf][nf], ah, &bhf[nf * 2]);   // hi*hi
                    mma_bf16(acc[mf][nf], ah, &blf[nf * 2]);   // hi*lo
                    mma_bf16(acc[mf][nf], al, &bhf[nf * 2]);   // lo*hi
                }
            }
        }
    }

    // ---- epilogue: bias [+relu][+mask] ----
    const int tq = lane >> 2;
    const int tr = lane & 3;
    float2 bv[4];
    #pragma unroll
    for (int nf = 0; nf < 4; nf++) {
        int col = bn + wn * 32 + nf * 8 + tr * 2;
        bv[nf].x = bias[col];
        bv[nf].y = bias[col + 1];
    }
    #pragma unroll
    for (int mf = 0; mf < 4; mf++) {
        #pragma unroll
        for (int half = 0; half < 2; half++) {
            int row = bm + wm * 64 + mf * 16 + tq + half * 8;
            float mv = (flags & 2) ? mask[row] : 1.0f;
            float* dst = C + (size_t)row * N + bn + wn * 32 + tr * 2;
            #pragma unroll
            for (int nf = 0; nf < 4; nf++) {
                float2 v;
                v.x = acc[mf][nf][half * 2 + 0] + bv[nf].x;
                v.y = acc[mf][nf][half * 2 + 1] + bv[nf].y;
                if (flags & 1) { v.x = fmaxf(v.x, 0.f); v.y = fmaxf(v.y, 0.f); }
                v.x *= mv; v.y *= mv;
                *(float2*)(dst + nf * 8) = v;
            }
        }
    }
}

// ===========================================================================
// Combined-weight precompute -> bf16 hi/lo planes (+ combined bias)
// ===========================================================================
__global__ void __launch_bounds__(256)
comb_kernel(const float* __restrict__ Wq, const float* __restrict__ Wqf,
            const float* __restrict__ Wk, const float* __restrict__ Wkf,
            const float* __restrict__ bq, const float* __restrict__ bk)
{
    const int isk = blockIdx.z;
    const float* Wbig = isk ? Wk : Wq;
    const float* Wf   = isk ? Wkf : Wqf;
    __nv_bfloat16* outh = isk ? g_Wkch : g_Wqch;
    __nv_bfloat16* outl = isk ? g_Wkcl : g_Wqcl;
    const int h  = blockIdx.y;
    const int e0 = blockIdx.x * 128;

    __shared__ float Wfs[FDIM][HDIM + 1];
    __shared__ float Ws[16][128];

    const int tid = threadIdx.x;
    for (int idx = tid; idx < FDIM * HDIM; idx += 256)
        Wfs[idx >> 7][idx & 127] = Wf[idx];
    __syncthreads();

    if (blockIdx.x == 0 && tid < FDIM) {
        const float* b = isk ? bk : bq;
        float s = 0.f;
        for (int d = 0; d < HDIM; d++) s += Wfs[tid][d] * b[h * HDIM + d];
        (isk ? g_bkc : g_bqc)[h * FDIM + tid] = s;
    }

    const int f  = tid & 63;
    const int eg = tid >> 6;
    float acc[32];
    #pragma unroll
    for (int j = 0; j < 32; j++) acc[j] = 0.f;

    for (int d0 = 0; d0 < HDIM; d0 += 16) {
        __syncthreads();
        #pragma unroll
        for (int i = 0; i < 2; i++) {
            int idx = tid + 256 * i;
            int dd  = idx >> 5;
            int c4  = (idx & 31) * 4;
            *(float4*)&Ws[dd][c4] =
                *(const float4*)(Wbig + (size_t)(h * HDIM + d0 + dd) * HID + e0 + c4);
        }
        __syncthreads();
        #pragma unroll
        for (int dd = 0; dd < 16; dd++) {
            float wf = Wfs[f][d0 + dd];
            #pragma unroll
            for (int j = 0; j < 32; j++)
                acc[j] += wf * Ws[dd][eg * 32 + j];
        }
    }
    #pragma unroll
    for (int j = 0; j < 32; j++) {
        size_t idx = (size_t)(h * FDIM + f) * HID + e0 + eg * 32 + j;
        float v = acc[j];
        __nv_bfloat16 hb = __float2bfloat16(v);
        outh[idx] = hb;
        outl[idx] = __float2bfloat16(v - __bfloat162float(hb));
    }
}

// ===========================================================================
// kv partial + per-chunk k' column sums (deterministic split-K)
// ===========================================================================
__global__ void __launch_bounds__(256)
kv_partial_kernel()
{
    __shared__ float ks[32][FDIM];
    __shared__ float vs[32][HDIM];

    const int tid = threadIdx.x;
    const int bh  = blockIdx.y;
    const int b   = bh >> 4, h = bh & 15;
    const int s0  = blockIdx.x * (SEQ / KVCH);
    const int fg  = tid >> 4;
    const int eg  = tid & 15;

    float acc[4][8];
    #pragma unroll
    for (int i = 0; i < 4; i++)
        #pragma unroll
        for (int j = 0; j < 8; j++) acc[i][j] = 0.f;
    float ksacc = 0.f;

    for (int ss = 0; ss < SEQ / KVCH; ss += 32) {
        #pragma unroll
        for (int i = 0; i < 2; i++) {
            int idx = tid + 256 * i;
            int sr  = idx >> 4;
            int c4  = (idx & 15) * 4;
            *(float4*)&ks[sr][c4] = *(const float4*)(
                g_kp + ((size_t)(b * SEQ + s0 + ss + sr) * NHEADS + h) * FDIM + c4);
        }
        #pragma unroll
        for (int i = 0; i < 4; i++) {
            int idx = tid + 256 * i;
            int sr  = idx >> 5;
            int c4  = (idx & 31) * 4;
            *(float4*)&vs[sr][c4] = *(const float4*)(
                g_V + (size_t)(b * SEQ + s0 + ss + sr) * HID + h * HDIM + c4);
        }
        __syncthreads();

        #pragma unroll 4
        for (int s = 0; s < 32; s++) {
            float a[4];
            *(float4*)a = *(const float4*)&ks[s][fg * 4];
            float bb[8];
            *(float4*)&bb[0] = *(const float4*)&vs[s][eg * 8];
            *(float4*)&bb[4] = *(const float4*)&vs[s][eg * 8 + 4];
            #pragma unroll
            for (int i = 0; i < 4; i++)
                #pragma unroll
                for (int j = 0; j < 8; j++) acc[i][j] += a[i] * bb[j];
        }
        if (tid < FDIM) {
            #pragma unroll 8
            for (int s = 0; s < 32; s++) ksacc += ks[s][tid];
        }
        __syncthreads();
    }

    float* dst = g_kvpart + ((size_t)blockIdx.x * BHEADS + bh) * FDIM * HDIM;
    #pragma unroll
    for (int i = 0; i < 4; i++)
        #pragma unroll
        for (int j = 0; j < 8; j++)
            dst[(fg * 4 + i) * HDIM + eg * 8 + j] = acc[i][j];
    if (tid < FDIM)
        g_kspart[(blockIdx.x * BHEADS + bh) * FDIM + tid] = ksacc;
}

__global__ void __launch_bounds__(256)
kv_reduce_kernel()
{
    int i = blockIdx.x * 256 + threadIdx.x;
    float s = 0.f;
    #pragma unroll
    for (int c = 0; c < KVCH; c++) s += g_kvpart[(size_t)c * KVELEM + i];
    g_kv[i] = s;
}

__global__ void __launch_bounds__(256)
ksum_reduce_kernel()
{
    int i = blockIdx.x * 256 + threadIdx.x;
    float s = 0.f;
    #pragma unroll
    for (int c = 0; c < KVCH; c++) s += g_kspart[c * BHEADS * FDIM + i];
    g_ksum[i] = s;
}

// ===========================================================================
// qkv + normalize -> bf16 hi/lo planes. 128 rows/block, 4 rows/thread
// (kv-tile LDS amortized 4x). Dynamic smem: kvs 32KB + qs(stride 68) 34KB.
// ===========================================================================
#define QKV_SMEM (64 * 128 * 4 + 128 * 68 * 4 + FDIM * 4)   // 67840

__global__ void __launch_bounds__(256)
qkv_kernel()
{
    extern __shared__ float dsm[];
    float* kvs = dsm;                         // [64][128]
    float* qs  = dsm + 64 * 128;              // [128][68] (padded stride)
    float* kss = dsm + 64 * 128 + 128 * 68;   // [64]

    const int tid = threadIdx.x;
    const int h   = blockIdx.y;
    const int bs0 = blockIdx.x * 128;         // SEQ%128==0: no batch crossing
    const int b   = bs0 / SEQ;
    const int bh  = b * NHEADS + h;

    #pragma unroll
    for (int i = 0; i < 8; i++) {
        int idx = tid + 256 * i;              // 2048 float4s (64x128)
        int fr  = idx >> 5;
        int c4  = (idx & 31) * 4;
        *(float4*)&kvs[fr * 128 + c4] = *(const float4*)(
            g_kv + (size_t)bh * FDIM * HDIM + fr * HDIM + c4);
    }
    #pragma unroll
    for (int i = 0; i < 8; i++) {
        int idx = tid + 256 * i;              // 2048 float4s (128x64)
        int sr  = idx >> 4;
        int c4  = (idx & 15) * 4;
        *(float4*)&qs[sr * 68 + c4] = *(const float4*)(
            g_qp + ((size_t)(bs0 + sr) * NHEADS + h) * FDIM + c4);
    }
    if (tid < FDIM) kss[tid] = g_ksum[bh * FDIM + tid];
    __syncthreads();

    const int e0 = (tid & 7) * 16;
    const int r0 = (tid >> 3) * 4;

    float accv[4][16];
    float den[4] = {0.f, 0.f, 0.f, 0.f};
    #pragma unroll
    for (int i = 0; i < 4; i++)
        #pragma unroll
        for (int j = 0; j < 16; j++) accv[i][j] = 0.f;

    #pragma unroll 2
    for (int f = 0; f < FDIM; f++) {
        float kvv[16];
        *(float4*)&kvv[0]  = *(const float4*)&kvs[f * 128 + e0];
        *(float4*)&kvv[4]  = *(const float4*)&kvs[f * 128 + e0 + 4];
        *(float4*)&kvv[8]  = *(const float4*)&kvs[f * 128 + e0 + 8];
        *(float4*)&kvv[12] = *(const float4*)&kvs[f * 128 + e0 + 12];
        const float ksf = kss[f];
        #pragma unroll
        for (int i = 0; i < 4; i++) {
            float q = qs[(r0 + i) * 68 + f];
            den[i] += q * ksf;
            #pragma unroll
            for (int j = 0; j < 16; j++) accv[i][j] += q * kvv[j];
        }
    }

    #pragma unroll
    for (int i = 0; i < 4; i++) {
        const float inv = 1.0f / (den[i] + 1e-8f);
        uint32_t H[8], L[8];
        #pragma unroll
        for (int p = 0; p < 8; p++)
            split_pack(accv[i][2 * p] * inv, accv[i][2 * p + 1] * inv, H[p], L[p]);
        size_t didx = (size_t)(bs0 + r0 + i) * HID + h * HDIM + e0;
        *(uint4*)&g_ah[didx]     = make_uint4(H[0], H[1], H[2], H[3]);
        *(uint4*)&g_ah[didx + 8] = make_uint4(H[4], H[5], H[6], H[7]);
        *(uint4*)&g_al[didx]     = make_uint4(L[0], L[1], L[2], L[3]);
        *(uint4*)&g_al[didx + 8] = make_uint4(L[4], L[5], L[6], L[7]);
    }
}

// ===========================================================================
extern "C" void kernel_launch(void* const* d_in, const int* in_sizes, int n_in,
                              void* d_out, int out_size)
{
    const float* query = (const float*)d_in[0];
    const float* key_  = (const float*)d_in[1];
    const float* value = (const float*)d_in[2];
    const float* mask  = (const float*)d_in[3];
    const float* Wq    = (const float*)d_in[4];
    const float* bq    = (const float*)d_in[5];
    const float* Wk    = (const float*)d_in[6];
    const float* bk    = (const float*)d_in[7];
    const float* Wv    = (const float*)d_in[8];
    const float* bv    = (const float*)d_in[9];
    const float* Wqf   = (const float*)d_in[10];
    const float* Wkf   = (const float*)d_in[11];
    const float* Wo    = (const float*)d_in[12];
    const float* bo    = (const float*)d_in[13];
    float* out = (float*)d_out;

    cudaFuncSetAttribute(gemm_tc, cudaFuncAttributeMaxDynamicSharedMemorySize, GSMEM);
    cudaFuncSetAttribute(qkv_kernel, cudaFuncAttributeMaxDynamicSharedMemorySize, QKV_SMEM);

    const int nbig = (MROWS * HID) / 8;      // 4194304
    const int nw   = (HID * HID) / 8;        // 524288

    comb_kernel<<<dim3(HID / 128, NHEADS, 2), 256>>>(Wq, Wqf, Wk, Wkf, bq, bk);   // 0
    conv3_kernel<<<dim3((nbig + 255) / 256, 3), 256>>>(query, key_, value, nbig); // 1
    convw_kernel<<<(nw + 255) / 256, 256>>>(Wv, 0, nw);                           // 2
    // merged q' / k' / V GEMMs
    gemm_tc<<<4096, 256, GSMEM>>>(0, bv, nullptr, nullptr, mask);                 // 3
    convw_kernel<<<(nw + 255) / 256, 256>>>(Wo, 1, nw);                           // 4

    kv_partial_kernel<<<dim3(KVCH, BHEADS), 256>>>();                             // 5
    kv_reduce_kernel<<<KVELEM / 256, 256>>>();                                    // 6
    ksum_reduce_kernel<<<(BHEADS * FDIM) / 256, 256>>>();                         // 7
    qkv_kernel<<<dim3(MROWS / 128, NHEADS), 256, QKV_SMEM>>>();                   // 8

    // out = attn @ Wo^T + bo
    gemm_tc<<<2048, 256, GSMEM>>>(1, nullptr, bo, out, mask);                     // 9
}

// round 10
// speedup vs baseline: 1.7675x; 1.5170x over previous
#include <cuda_runtime.h>
#include <cuda_fp16.h>
#include <cstdint>

// Problem constants (fixed by the dataset)
#define BATCH   4
#define SEQ     4096
#define HID     2048
#define NHEADS  16
#define HDIM    128
#define FDIM    64
#define MROWS   (BATCH * SEQ)          // 16384
#define M2      (MROWS * NHEADS)       // 262144
#define BHEADS  (BATCH * NHEADS)       // 64
#define KVCH    16
#define KVELEM  (BHEADS * FDIM * HDIM) // 524288
#define NQP     (NHEADS * FDIM)        // 1024

// ---------------- scratch (static device globals; no allocation) -----------
__device__ float g_V[(size_t)MROWS * HID];
__device__ float g_qp[(size_t)M2 * FDIM];
__device__ float g_kp[(size_t)M2 * FDIM];
__device__ float g_kvpart[(size_t)KVCH * KVELEM];
__device__ float g_kv[KVELEM];
__device__ float g_kspart[KVCH * BHEADS * FDIM];
__device__ float g_ksum[BHEADS * FDIM];
__device__ float g_bqc[NQP];
__device__ float g_bkc[NQP];
// fp16 activations (single plane) + fp16 hi/lo weight planes
__device__ __half g_q16[(size_t)MROWS * HID];
__device__ __half g_k16[(size_t)MROWS * HID];
__device__ __half g_v16[(size_t)MROWS * HID];
__device__ __half g_a16[(size_t)MROWS * HID];
__device__ __half g_Wvh[(size_t)HID * HID],  g_Wvl[(size_t)HID * HID];
__device__ __half g_Woh[(size_t)HID * HID],  g_Wol[(size_t)HID * HID];
__device__ __half g_Wqch[(size_t)NQP * HID], g_Wqcl[(size_t)NQP * HID];
__device__ __half g_Wkch[(size_t)NQP * HID], g_Wkcl[(size_t)NQP * HID];

// =========================== helpers =======================================
__device__ __forceinline__ uint32_t smem_u32(const void* p) {
    uint32_t a;
    asm("{ .reg .u64 t; cvta.to.shared.u64 t, %1; cvt.u32.u64 %0, t; }"
        : "=r"(a) : "l"(p));
    return a;
}
#define SMEM_SWIZZLE_128B(off) ((off) ^ (((off) >> 3) & 0x70))

__device__ __forceinline__ void cp16(uint32_t dst, const void* src) {
    asm volatile("cp.async.cg.shared.global [%0], [%1], 16;"
                 :: "r"(dst), "l"(src) : "memory");
}
#define CP_COMMIT() asm volatile("cp.async.commit_group;" ::: "memory")
#define CP_WAIT1()  asm volatile("cp.async.wait_group 1;" ::: "memory")

__device__ __forceinline__ void ldsm_x4(uint32_t& r0, uint32_t& r1,
                                        uint32_t& r2, uint32_t& r3,
                                        uint32_t addr) {
    asm volatile("ldmatrix.sync.aligned.m8n8.x4.shared.b16 {%0,%1,%2,%3}, [%4];"
                 : "=r"(r0), "=r"(r1), "=r"(r2), "=r"(r3) : "r"(addr));
}
__device__ __forceinline__ void mma_f16(float* d, const uint32_t* a,
                                        const uint32_t* b) {
    asm volatile(
        "mma.sync.aligned.m16n8k16.row.col.f32.f16.f16.f32 "
        "{%0,%1,%2,%3}, {%4,%5,%6,%7}, {%8,%9}, {%0,%1,%2,%3};"
        : "+f"(d[0]), "+f"(d[1]), "+f"(d[2]), "+f"(d[3])
        : "r"(a[0]), "r"(a[1]), "r"(a[2]), "r"(a[3]), "r"(b[0]), "r"(b[1]));
}
__device__ __forceinline__ uint32_t pack_h2(float x, float y) {
    __half2 h = __floats2half2_rn(x, y);
    return *reinterpret_cast<uint32_t*>(&h);
}
__device__ __forceinline__ void split_h2(float x, float y,
                                         uint32_t& h, uint32_t& l) {
    __half hx = __float2half_rn(x), hy = __float2half_rn(y);
    __half lx = __float2half_rn(x - __half2float(hx));
    __half ly = __float2half_rn(y - __half2float(hy));
    h = (uint32_t)__half_as_ushort(hx) | ((uint32_t)__half_as_ushort(hy) << 16);
    l = (uint32_t)__half_as_ushort(lx) | ((uint32_t)__half_as_ushort(ly) << 16);
}

// ===========================================================================
// fp32 -> fp16 conversions
// ===========================================================================
__global__ void __launch_bounds__(256)
conv3_kernel(const float* __restrict__ q, const float* __restrict__ k,
             const float* __restrict__ v, int n8)
{
    const int sel = blockIdx.y;
    const float* src = (sel == 0) ? q : (sel == 1) ? k : v;
    __half* dst = (sel == 0) ? g_q16 : (sel == 1) ? g_k16 : g_v16;
    int i = blockIdx.x * 256 + threadIdx.x;
    if (i >= n8) return;
    const float4* s4 = (const float4*)src + (size_t)i * 2;
    float4 v0 = s4[0], v1 = s4[1];
    uint4 p;
    p.x = pack_h2(v0.x, v0.y);
    p.y = pack_h2(v0.z, v0.w);
    p.z = pack_h2(v1.x, v1.y);
    p.w = pack_h2(v1.z, v1.w);
    *(uint4*)(dst + (size_t)i * 8) = p;
}

__global__ void __launch_bounds__(256)
convw_kernel(const float* __restrict__ src, int sel, int n8)
{
    __half* dh = sel ? g_Woh : g_Wvh;
    __half* dl = sel ? g_Wol : g_Wvl;
    int i = blockIdx.x * 256 + threadIdx.x;
    if (i >= n8) return;
    const float4* s4 = (const float4*)src + (size_t)i * 2;
    float4 v0 = s4[0], v1 = s4[1];
    uint32_t h[4], l[4];
    split_h2(v0.x, v0.y, h[0], l[0]);
    split_h2(v0.z, v0.w, h[1], l[1]);
    split_h2(v1.x, v1.y, h[2], l[2]);
    split_h2(v1.z, v1.w, h[3], l[3]);
    *(uint4*)(dh + (size_t)i * 8) = make_uint4(h[0], h[1], h[2], h[3]);
    *(uint4*)(dl + (size_t)i * 8) = make_uint4(l[0], l[1], l[2], l[3]);
}

// ===========================================================================
// Tensor-core GEMM: A single fp16 plane, W = fp16 hi+lo planes, 2 MMA passes.
//   C = A @ (Wh+Wl)^T + bias [,relu][,row-mask]
// 128x128 tile, TILE_K=64 (128B rows, SW128), cp.async double-buffer,
// 256 threads, 2 CTA/SM. mode 0: merged q'/k'/V (grid 4096); mode 1: O (2048).
// ===========================================================================
#define TILE_K   64
#define CHUNKS   (HID / TILE_K)   // 32
#define OFF_A    0
#define OFF_BH   16384
#define OFF_BL   32768
#define STG      49152            // A 16KB + Bh 16KB + Bl 16KB
#define GSMEM    (2 * STG)        // 98304

__device__ __forceinline__ void stage_load(
    uint32_t sbuf, const __half* pa, const __half* pbh, const __half* pbl,
    int tid)
{
    #pragma unroll
    for (int i = 0; i < 4; i++) {
        int idx = tid + 256 * i;          // 0..1023
        int r   = idx >> 3;               // 0..127
        int q   = idx & 7;                // 16B chunk
        uint32_t off = SMEM_SWIZZLE_128B((uint32_t)(r * 128 + q * 16));
        size_t g = (size_t)r * HID + q * 8;
        cp16(sbuf + OFF_A  + off, pa  + g);
        cp16(sbuf + OFF_BH + off, pbh + g);
        cp16(sbuf + OFF_BL + off, pbl + g);
    }
}

__global__ void __launch_bounds__(256, 2)
gemm_tc(int mode, const float* __restrict__ bvv, const float* __restrict__ boo,
        float* __restrict__ outp, const float* __restrict__ mask)
{
    extern __shared__ char smem[];

    // ---- block decode ----
    int op, bx, by;
    if (mode == 0) {
        int b = blockIdx.x;
        if (b < 1024)      { op = 0; bx = b & 7; by = b >> 3; }
        else if (b < 2048) { b -= 1024; op = 1; bx = b & 7; by = b >> 3; }
        else               { b -= 2048; op = 2; bx = b & 15; by = b >> 4; }
    } else {
        int b = blockIdx.x;  op = 3; bx = b & 15; by = b >> 4;
    }
    const __half *A16, *Wh, *Wl;
    const float* bias;
    float* C;
    int N, flags;
    switch (op) {
        case 0: A16 = g_q16; Wh = g_Wqch; Wl = g_Wqcl;
                bias = g_bqc; C = g_qp; N = NQP; flags = 1; break;
        case 1: A16 = g_k16; Wh = g_Wkch; Wl = g_Wkcl;
                bias = g_bkc; C = g_kp; N = NQP; flags = 3; break;
        case 2: A16 = g_v16; Wh = g_Wvh; Wl = g_Wvl;
                bias = bvv; C = g_V; N = HID; flags = 0; break;
        default: A16 = g_a16; Wh = g_Woh; Wl = g_Wol;
                bias = boo; C = outp; N = HID; flags = 0; break;
    }
    const int bn = bx * 128;
    const int bm = by * 128;

    const uint32_t sb = smem_u32(smem);
    const int tid  = threadIdx.x;
    const int lane = tid & 31;
    const int wid  = tid >> 5;
    const int wm   = wid >> 2;         // 0..1  (M: 2 x 64)
    const int wn   = wid & 3;          // 0..3  (N: 4 x 32)

    const __half* Abase = A16 + (size_t)bm * HID;
    const __half* Bhb   = Wh  + (size_t)bn * HID;
    const __half* Blb   = Wl  + (size_t)bn * HID;

    const uint32_t a_row  = (uint32_t)(wm * 64 + (lane & 15));
    const uint32_t a_kofs = (uint32_t)((lane >> 4) * 16);
    const uint32_t b_row  = (uint32_t)(wn * 32 + (lane & 7) + ((lane & 16) >> 1));
    const uint32_t b_kofs = (uint32_t)((lane & 8) * 2);

    float acc[4][4][4];
    #pragma unroll
    for (int mf = 0; mf < 4; mf++)
        #pragma unroll
        for (int nf = 0; nf < 4; nf++)
            #pragma unroll
            for (int j = 0; j < 4; j++) acc[mf][nf][j] = 0.f;

    // prologue: both stages in flight
    stage_load(sb + 0 * STG, Abase, Bhb, Blb, tid);
    CP_COMMIT();
    stage_load(sb + 1 * STG, Abase + TILE_K, Bhb + TILE_K, Blb + TILE_K, tid);
    CP_COMMIT();

    #pragma unroll 1
    for (int c = 0; c < CHUNKS; c++) {
        CP_WAIT1();            // stage c landed (only c+1 may pend)
        __syncthreads();

        const uint32_t sbase = sb + (c & 1) * STG;
        #pragma unroll
        for (int ks = 0; ks < 4; ks++) {
            const uint32_t kb = (uint32_t)(ks * 32);
            uint32_t bhf[8], blf[8];
            #pragma unroll
            for (int nf2 = 0; nf2 < 2; nf2++) {
                uint32_t off = SMEM_SWIZZLE_128B(
                    (b_row + nf2 * 16) * 128 + kb + b_kofs);
                ldsm_x4(bhf[nf2*4+0], bhf[nf2*4+1], bhf[nf2*4+2], bhf[nf2*4+3],
                        sbase + OFF_BH + off);
                ldsm_x4(blf[nf2*4+0], blf[nf2*4+1], blf[nf2*4+2], blf[nf2*4+3],
                        sbase + OFF_BL + off);
            }
            #pragma unroll
            for (int mf = 0; mf < 4; mf++) {
                uint32_t aoff = SMEM_SWIZZLE_128B(
                    (a_row + mf * 16) * 128 + kb + a_kofs);
                uint32_t ah[4];
                ldsm_x4(ah[0], ah[1], ah[2], ah[3], sbase + OFF_A + aoff);
                #pragma unroll
                for (int nf = 0; nf < 4; nf++) {
                    mma_f16(acc[mf][nf], ah, &bhf[nf * 2]);   // A * W_hi
                    mma_f16(acc[mf][nf], ah, &blf[nf * 2]);   // A * W_lo
                }
            }
        }

        __syncthreads();       // all reads of stage c done
        if (c + 2 < CHUNKS)
            stage_load(sb + (c & 1) * STG, Abase + (c + 2) * TILE_K,
                       Bhb + (c + 2) * TILE_K, Blb + (c + 2) * TILE_K, tid);
        CP_COMMIT();           // empty commits are legal no-ops
    }

    // ---- epilogue: bias [+relu][+mask] ----
    const int tq = lane >> 2;
    const int tr = lane & 3;
    float2 bv[4];
    #pragma unroll
    for (int nf = 0; nf < 4; nf++) {
        int col = bn + wn * 32 + nf * 8 + tr * 2;
        bv[nf].x = bias[col];
        bv[nf].y = bias[col + 1];
    }
    #pragma unroll
    for (int mf = 0; mf < 4; mf++) {
        #pragma unroll
        for (int half = 0; half < 2; half++) {
            int row = bm + wm * 64 + mf * 16 + tq + half * 8;
            float mv = (flags & 2) ? mask[row] : 1.0f;
            float* dst = C + (size_t)row * N + bn + wn * 32 + tr * 2;
            #pragma unroll
            for (int nf = 0; nf < 4; nf++) {
                float2 v;
                v.x = acc[mf][nf][half * 2 + 0] + bv[nf].x;
                v.y = acc[mf][nf][half * 2 + 1] + bv[nf].y;
                if (flags & 1) { v.x = fmaxf(v.x, 0.f); v.y = fmaxf(v.y, 0.f); }
                v.x *= mv; v.y *= mv;
                *(float2*)(dst + nf * 8) = v;
            }
        }
    }
}

// ===========================================================================
// Combined-weight precompute -> fp16 hi/lo planes (+ combined bias)
// ===========================================================================
__global__ void __launch_bounds__(256)
comb_kernel(const float* __restrict__ Wq, const float* __restrict__ Wqf,
            const float* __restrict__ Wk, const float* __restrict__ Wkf,
            const float* __restrict__ bq, const float* __restrict__ bk)
{
    const int isk = blockIdx.z;
    const float* Wbig = isk ? Wk : Wq;
    const float* Wf   = isk ? Wkf : Wqf;
    __half* outh = isk ? g_Wkch : g_Wqch;
    __half* outl = isk ? g_Wkcl : g_Wqcl;
    const int h  = blockIdx.y;
    const int e0 = blockIdx.x * 128;

    __shared__ float Wfs[FDIM][HDIM + 1];
    __shared__ float Ws[16][128];

    const int tid = threadIdx.x;
    for (int idx = tid; idx < FDIM * HDIM; idx += 256)
        Wfs[idx >> 7][idx & 127] = Wf[idx];
    __syncthreads();

    if (blockIdx.x == 0 && tid < FDIM) {
        const float* b = isk ? bk : bq;
        float s = 0.f;
        for (int d = 0; d < HDIM; d++) s += Wfs[tid][d] * b[h * HDIM + d];
        (isk ? g_bkc : g_bqc)[h * FDIM + tid] = s;
    }

    const int f  = tid & 63;
    const int eg = tid >> 6;
    float acc[32];
    #pragma unroll
    for (int j = 0; j < 32; j++) acc[j] = 0.f;

    for (int d0 = 0; d0 < HDIM; d0 += 16) {
        __syncthreads();
        #pragma unroll
        for (int i = 0; i < 2; i++) {
            int idx = tid + 256 * i;
            int dd  = idx >> 5;
            int c4  = (idx & 31) * 4;
            *(float4*)&Ws[dd][c4] =
                *(const float4*)(Wbig + (size_t)(h * HDIM + d0 + dd) * HID + e0 + c4);
        }
        __syncthreads();
        #pragma unroll
        for (int dd = 0; dd < 16; dd++) {
            float wf = Wfs[f][d0 + dd];
            #pragma unroll
            for (int j = 0; j < 32; j++)
                acc[j] += wf * Ws[dd][eg * 32 + j];
        }
    }
    #pragma unroll
    for (int j = 0; j < 32; j++) {
        size_t idx = (size_t)(h * FDIM + f) * HID + e0 + eg * 32 + j;
        float v = acc[j];
        __half hb = __float2half_rn(v);
        outh[idx] = hb;
        outl[idx] = __float2half_rn(v - __half2float(hb));
    }
}

// ===========================================================================
// kv partial + per-chunk k' column sums (deterministic split-K)
// ===========================================================================
__global__ void __launch_bounds__(256)
kv_partial_kernel()
{
    __shared__ float ks[32][FDIM];
    __shared__ float vs[32][HDIM];

    const int tid = threadIdx.x;
    const int bh  = blockIdx.y;
    const int b   = bh >> 4, h = bh & 15;
    const int s0  = blockIdx.x * (SEQ / KVCH);
    const int fg  = tid >> 4;
    const int eg  = tid & 15;

    float acc[4][8];
    #pragma unroll
    for (int i = 0; i < 4; i++)
        #pragma unroll
        for (int j = 0; j < 8; j++) acc[i][j] = 0.f;
    float ksacc = 0.f;

    for (int ss = 0; ss < SEQ / KVCH; ss += 32) {
        #pragma unroll
        for (int i = 0; i < 2; i++) {
            int idx = tid + 256 * i;
            int sr  = idx >> 4;
            int c4  = (idx & 15) * 4;
            *(float4*)&ks[sr][c4] = *(const float4*)(
                g_kp + ((size_t)(b * SEQ + s0 + ss + sr) * NHEADS + h) * FDIM + c4);
        }
        #pragma unroll
        for (int i = 0; i < 4; i++) {
            int idx = tid + 256 * i;
            int sr  = idx >> 5;
            int c4  = (idx & 31) * 4;
            *(float4*)&vs[sr][c4] = *(const float4*)(
                g_V + (size_t)(b * SEQ + s0 + ss + sr) * HID + h * HDIM + c4);
        }
        __syncthreads();

        #pragma unroll 4
        for (int s = 0; s < 32; s++) {
            float a[4];
            *(float4*)a = *(const float4*)&ks[s][fg * 4];
            float bb[8];
            *(float4*)&bb[0] = *(const float4*)&vs[s][eg * 8];
            *(float4*)&bb[4] = *(const float4*)&vs[s][eg * 8 + 4];
            #pragma unroll
            for (int i = 0; i < 4; i++)
                #pragma unroll
                for (int j = 0; j < 8; j++) acc[i][j] += a[i] * bb[j];
        }
        if (tid < FDIM) {
            #pragma unroll 8
            for (int s = 0; s < 32; s++) ksacc += ks[s][tid];
        }
        __syncthreads();
    }

    float* dst = g_kvpart + ((size_t)blockIdx.x * BHEADS + bh) * FDIM * HDIM;
    #pragma unroll
    for (int i = 0; i < 4; i++)
        #pragma unroll
        for (int j = 0; j < 8; j++)
            dst[(fg * 4 + i) * HDIM + eg * 8 + j] = acc[i][j];
    if (tid < FDIM)
        g_kspart[(blockIdx.x * BHEADS + bh) * FDIM + tid] = ksacc;
}

__global__ void __launch_bounds__(256)
kv_reduce_kernel()
{
    int i = blockIdx.x * 256 + threadIdx.x;
    float s = 0.f;
    #pragma unroll
    for (int c = 0; c < KVCH; c++) s += g_kvpart[(size_t)c * KVELEM + i];
    g_kv[i] = s;
}

__global__ void __launch_bounds__(256)
ksum_reduce_kernel()
{
    int i = blockIdx.x * 256 + threadIdx.x;
    float s = 0.f;
    #pragma unroll
    for (int c = 0; c < KVCH; c++) s += g_kspart[c * BHEADS * FDIM + i];
    g_ksum[i] = s;
}

// ===========================================================================
// qkv + normalize -> single fp16 plane (input to O projection)
// 128 rows/block, 4 rows/thread; qs padded to stride 68.
// ===========================================================================
#define QKV_SMEM (64 * 128 * 4 + 128 * 68 * 4 + FDIM * 4)   // 67840

__global__ void __launch_bounds__(256)
qkv_kernel()
{
    extern __shared__ float dsm[];
    float* kvs = dsm;                         // [64][128]
    float* qs  = dsm + 64 * 128;              // [128][68]
    float* kss = dsm + 64 * 128 + 128 * 68;   // [64]

    const int tid = threadIdx.x;
    const int h   = blockIdx.y;
    const int bs0 = blockIdx.x * 128;
    const int b   = bs0 / SEQ;
    const int bh  = b * NHEADS + h;

    #pragma unroll
    for (int i = 0; i < 8; i++) {
        int idx = tid + 256 * i;
        int fr  = idx >> 5;
        int c4  = (idx & 31) * 4;
        *(float4*)&kvs[fr * 128 + c4] = *(const float4*)(
            g_kv + (size_t)bh * FDIM * HDIM + fr * HDIM + c4);
    }
    #pragma unroll
    for (int i = 0; i < 8; i++) {
        int idx = tid + 256 * i;
        int sr  = idx >> 4;
        int c4  = (idx & 15) * 4;
        *(float4*)&qs[sr * 68 + c4] = *(const float4*)(
            g_qp + ((size_t)(bs0 + sr) * NHEADS + h) * FDIM + c4);
    }
    if (tid < FDIM) kss[tid] = g_ksum[bh * FDIM + tid];
    __syncthreads();

    const int e0 = (tid & 7) * 16;
    const int r0 = (tid >> 3) * 4;

    float accv[4][16];
    float den[4] = {0.f, 0.f, 0.f, 0.f};
    #pragma unroll
    for (int i = 0; i < 4; i++)
        #pragma unroll
        for (int j = 0; j < 16; j++) accv[i][j] = 0.f;

    #pragma unroll 2
    for (int f = 0; f < FDIM; f++) {
        float kvv[16];
        *(float4*)&kvv[0]  = *(const float4*)&kvs[f * 128 + e0];
        *(float4*)&kvv[4]  = *(const float4*)&kvs[f * 128 + e0 + 4];
        *(float4*)&kvv[8]  = *(const float4*)&kvs[f * 128 + e0 + 8];
        *(float4*)&kvv[12] = *(const float4*)&kvs[f * 128 + e0 + 12];
        const float ksf = kss[f];
        #pragma unroll
        for (int i = 0; i < 4; i++) {
            float q = qs[(r0 + i) * 68 + f];
            den[i] += q * ksf;
            #pragma unroll
            for (int j = 0; j < 16; j++) accv[i][j] += q * kvv[j];
        }
    }

    #pragma unroll
    for (int i = 0; i < 4; i++) {
        const float inv = 1.0f / (den[i] + 1e-8f);
        uint32_t P[8];
        #pragma unroll
        for (int p = 0; p < 8; p++)
            P[p] = pack_h2(accv[i][2 * p] * inv, accv[i][2 * p + 1] * inv);
        size_t didx = (size_t)(bs0 + r0 + i) * HID + h * HDIM + e0;
        *(uint4*)&g_a16[didx]     = make_uint4(P[0], P[1], P[2], P[3]);
        *(uint4*)&g_a16[didx + 8] = make_uint4(P[4], P[5], P[6], P[7]);
    }
}

// ===========================================================================
extern "C" void kernel_launch(void* const* d_in, const int* in_sizes, int n_in,
                              void* d_out, int out_size)
{
    const float* query = (const float*)d_in[0];
    const float* key_  = (const float*)d_in[1];
    const float* value = (const float*)d_in[2];
    const float* mask  = (const float*)d_in[3];
    const float* Wq    = (const float*)d_in[4];
    const float* bq    = (const float*)d_in[5];
    const float* Wk    = (const float*)d_in[6];
    const float* bk    = (const float*)d_in[7];
    const float* Wv    = (const float*)d_in[8];
    const float* bv    = (const float*)d_in[9];
    const float* Wqf   = (const float*)d_in[10];
    const float* Wkf   = (const float*)d_in[11];
    const float* Wo    = (const float*)d_in[12];
    const float* bo    = (const float*)d_in[13];
    float* out = (float*)d_out;

    cudaFuncSetAttribute(gemm_tc, cudaFuncAttributeMaxDynamicSharedMemorySize, GSMEM);
    cudaFuncSetAttribute(qkv_kernel, cudaFuncAttributeMaxDynamicSharedMemorySize, QKV_SMEM);

    const int nbig = (MROWS * HID) / 8;      // 4194304
    const int nw   = (HID * HID) / 8;        // 524288

    comb_kernel<<<dim3(HID / 128, NHEADS, 2), 256>>>(Wq, Wqf, Wk, Wkf, bq, bk);   // 0
    conv3_kernel<<<dim3((nbig + 255) / 256, 3), 256>>>(query, key_, value, nbig); // 1
    convw_kernel<<<(nw + 255) / 256, 256>>>(Wv, 0, nw);                           // 2
    // merged q' / k' / V GEMMs
    gemm_tc<<<4096, 256, GSMEM>>>(0, bv, nullptr, nullptr, mask);                 // 3
    convw_kernel<<<(nw + 255) / 256, 256>>>(Wo, 1, nw);                           // 4

    kv_partial_kernel<<<dim3(KVCH, BHEADS), 256>>>();                             // 5
    kv_reduce_kernel<<<KVELEM / 256, 256>>>();                                    // 6
    ksum_reduce_kernel<<<(BHEADS * FDIM) / 256, 256>>>();                         // 7
    qkv_kernel<<<dim3(MROWS / 128, NHEADS), 256, QKV_SMEM>>>();                   // 8

    // out = attn @ Wo^T + bo
    gemm_tc<<<2048, 256, GSMEM>>>(1, nullptr, bo, out, mask);                     // 9
}

// round 12
// speedup vs baseline: 2.1036x; 1.1901x over previous
#include <cuda_runtime.h>
#include <cuda_fp16.h>
#include <cstdint>

// Problem constants (fixed by the dataset)
#define BATCH   4
#define SEQ     4096
#define HID     2048
#define NHEADS  16
#define HDIM    128
#define FDIM    64
#define MROWS   (BATCH * SEQ)          // 16384
#define M2      (MROWS * NHEADS)       // 262144
#define BHEADS  (BATCH * NHEADS)       // 64
#define KVCH    16
#define KVELEM  (BHEADS * FDIM * HDIM) // 524288
#define NQP     (NHEADS * FDIM)        // 1024

// ---------------- scratch (static device globals; no allocation) -----------
__device__ float g_kvpart[(size_t)KVCH * KVELEM];
__device__ float g_kspart[KVCH * BHEADS * FDIM];
__device__ float g_ksum[BHEADS * FDIM];
__device__ float g_bqc[NQP];
__device__ float g_bkc[NQP];
// fp16 activations (GEMM inputs)
__device__ __half g_q16[(size_t)MROWS * HID];
__device__ __half g_k16[(size_t)MROWS * HID];
__device__ __half g_v16[(size_t)MROWS * HID];
__device__ __half g_a16[(size_t)MROWS * HID];
// fp16 GEMM outputs
__device__ __half g_qp16[(size_t)M2 * FDIM];
__device__ __half g_kp16[(size_t)M2 * FDIM];
__device__ __half g_vo16[(size_t)MROWS * HID];
__device__ __half g_kv16T[(size_t)BHEADS * HDIM * FDIM];   // [bh][e][f]
// fp16 hi/lo weight planes
__device__ __half g_Wvh[(size_t)HID * HID],  g_Wvl[(size_t)HID * HID];
__device__ __half g_Woh[(size_t)HID * HID],  g_Wol[(size_t)HID * HID];
__device__ __half g_Wqch[(size_t)NQP * HID], g_Wqcl[(size_t)NQP * HID];
__device__ __half g_Wkch[(size_t)NQP * HID], g_Wkcl[(size_t)NQP * HID];

// =========================== helpers =======================================
__device__ __forceinline__ uint32_t smem_u32(const void* p) {
    uint32_t a;
    asm("{ .reg .u64 t; cvta.to.shared.u64 t, %1; cvt.u32.u64 %0, t; }"
        : "=r"(a) : "l"(p));
    return a;
}
#define SMEM_SWIZZLE_128B(off) ((off) ^ (((off) >> 3) & 0x70))

__device__ __forceinline__ void cp16(uint32_t dst, const void* src) {
    asm volatile("cp.async.cg.shared.global [%0], [%1], 16;"
                 :: "r"(dst), "l"(src) : "memory");
}
#define CP_COMMIT() asm volatile("cp.async.commit_group;" ::: "memory")
#define CP_WAIT1()  asm volatile("cp.async.wait_group 1;" ::: "memory")
#define CP_WAIT0()  asm volatile("cp.async.wait_group 0;" ::: "memory")

__device__ __forceinline__ void ldsm_x4(uint32_t& r0, uint32_t& r1,
                                        uint32_t& r2, uint32_t& r3,
                                        uint32_t addr) {
    asm volatile("ldmatrix.sync.aligned.m8n8.x4.shared.b16 {%0,%1,%2,%3}, [%4];"
                 : "=r"(r0), "=r"(r1), "=r"(r2), "=r"(r3) : "r"(addr));
}
__device__ __forceinline__ void ldsm_x4_t(uint32_t& r0, uint32_t& r1,
                                          uint32_t& r2, uint32_t& r3,
                                          uint32_t addr) {
    asm volatile("ldmatrix.sync.aligned.m8n8.x4.trans.shared.b16 {%0,%1,%2,%3}, [%4];"
                 : "=r"(r0), "=r"(r1), "=r"(r2), "=r"(r3) : "r"(addr));
}
__device__ __forceinline__ void mma_f16(float* d, const uint32_t* a,
                                        const uint32_t* b) {
    asm volatile(
        "mma.sync.aligned.m16n8k16.row.col.f32.f16.f16.f32 "
        "{%0,%1,%2,%3}, {%4,%5,%6,%7}, {%8,%9}, {%0,%1,%2,%3};"
        : "+f"(d[0]), "+f"(d[1]), "+f"(d[2]), "+f"(d[3])
        : "r"(a[0]), "r"(a[1]), "r"(a[2]), "r"(a[3]), "r"(b[0]), "r"(b[1]));
}
__device__ __forceinline__ uint32_t pack_h2(float x, float y) {
    __half2 h = __floats2half2_rn(x, y);
    return *reinterpret_cast<uint32_t*>(&h);
}
__device__ __forceinline__ void split_h2(float x, float y,
                                         uint32_t& h, uint32_t& l) {
    __half hx = __float2half_rn(x), hy = __float2half_rn(y);
    __half lx = __float2half_rn(x - __half2float(hx));
    __half ly = __float2half_rn(y - __half2float(hy));
    h = (uint32_t)__half_as_ushort(hx) | ((uint32_t)__half_as_ushort(hy) << 16);
    l = (uint32_t)__half_as_ushort(lx) | ((uint32_t)__half_as_ushort(ly) << 16);
}

// ===========================================================================
// fp32 -> fp16 conversions
// ===========================================================================
__global__ void __launch_bounds__(256)
conv3_kernel(const float* __restrict__ q, const float* __restrict__ k,
             const float* __restrict__ v, int n8)
{
    const int sel = blockIdx.y;
    const float* src = (sel == 0) ? q : (sel == 1) ? k : v;
    __half* dst = (sel == 0) ? g_q16 : (sel == 1) ? g_k16 : g_v16;
    int i = blockIdx.x * 256 + threadIdx.x;
    if (i >= n8) return;
    const float4* s4 = (const float4*)src + (size_t)i * 2;
    float4 v0 = s4[0], v1 = s4[1];
    uint4 p;
    p.x = pack_h2(v0.x, v0.y);
    p.y = pack_h2(v0.z, v0.w);
    p.z = pack_h2(v1.x, v1.y);
    p.w = pack_h2(v1.z, v1.w);
    *(uint4*)(dst + (size_t)i * 8) = p;
}

__global__ void __launch_bounds__(256)
convw_kernel(const float* __restrict__ src, int sel, int n8)
{
    __half* dh = sel ? g_Woh : g_Wvh;
    __half* dl = sel ? g_Wol : g_Wvl;
    int i = blockIdx.x * 256 + threadIdx.x;
    if (i >= n8) return;
    const float4* s4 = (const float4*)src + (size_t)i * 2;
    float4 v0 = s4[0], v1 = s4[1];
    uint32_t h[4], l[4];
    split_h2(v0.x, v0.y, h[0], l[0]);
    split_h2(v0.z, v0.w, h[1], l[1]);
    split_h2(v1.x, v1.y, h[2], l[2]);
    split_h2(v1.z, v1.w, h[3], l[3]);
    *(uint4*)(dh + (size_t)i * 8) = make_uint4(h[0], h[1], h[2], h[3]);
    *(uint4*)(dl + (size_t)i * 8) = make_uint4(l[0], l[1], l[2], l[3]);
}

// ===========================================================================
// Main tensor-core GEMM (fp16 A, fp16 hi+lo W, 2 MMA passes), 2 CTA/SM.
// mode 0: merged q'/k'/V (grid 4096, fp16 outputs); mode 1: O (2048, fp32 out)
// ===========================================================================
#define TILE_K   64
#define CHUNKS   (HID / TILE_K)   // 32
#define OFF_A    0
#define OFF_BH   16384
#define OFF_BL   32768
#define STG      49152
#define GSMEM    (2 * STG)        // 98304

__device__ __forceinline__ void stage_load(
    uint32_t sbuf, const __half* pa, const __half* pbh, const __half* pbl,
    int tid)
{
    #pragma unroll
    for (int i = 0; i < 4; i++) {
        int idx = tid + 256 * i;
        int r   = idx >> 3;
        int q   = idx & 7;
        uint32_t off = SMEM_SWIZZLE_128B((uint32_t)(r * 128 + q * 16));
        size_t g = (size_t)r * HID + q * 8;
        cp16(sbuf + OFF_A  + off, pa  + g);
        cp16(sbuf + OFF_BH + off, pbh + g);
        cp16(sbuf + OFF_BL + off, pbl + g);
    }
}

__global__ void __launch_bounds__(256, 2)
gemm_tc(int mode, const float* __restrict__ bvv, const float* __restrict__ boo,
        float* __restrict__ outp, const float* __restrict__ mask)
{
    extern __shared__ char smem[];

    int op, bx, by;
    if (mode == 0) {
        int b = blockIdx.x;
        if (b < 1024)      { op = 0; bx = b & 7; by = b >> 3; }
        else if (b < 2048) { b -= 1024; op = 1; bx = b & 7; by = b >> 3; }
        else               { b -= 2048; op = 2; bx = b & 15; by = b >> 4; }
    } else {
        int b = blockIdx.x;  op = 3; bx = b & 15; by = b >> 4;
    }
    const __half *A16, *Wh, *Wl;
    const float* bias;
    __half* C16 = nullptr;
    int N, flags;
    switch (op) {
        case 0: A16 = g_q16; Wh = g_Wqch; Wl = g_Wqcl;
                bias = g_bqc; C16 = g_qp16; N = NQP; flags = 1; break;
        case 1: A16 = g_k16; Wh = g_Wkch; Wl = g_Wkcl;
                bias = g_bkc; C16 = g_kp16; N = NQP; flags = 3; break;
        case 2: A16 = g_v16; Wh = g_Wvh; Wl = g_Wvl;
                bias = bvv; C16 = g_vo16; N = HID; flags = 0; break;
        default: A16 = g_a16; Wh = g_Woh; Wl = g_Wol;
                bias = boo; N = HID; flags = 0; break;
    }
    const int bn = bx * 128;
    const int bm = by * 128;

    const uint32_t sb = smem_u32(smem);
    const int tid  = threadIdx.x;
    const int lane = tid & 31;
    const int wid  = tid >> 5;
    const int wm   = wid >> 2;
    const int wn   = wid & 3;

    const __half* Abase = A16 + (size_t)bm * HID;
    const __half* Bhb   = Wh  + (size_t)bn * HID;
    const __half* Blb   = Wl  + (size_t)bn * HID;

    const uint32_t a_row  = (uint32_t)(wm * 64 + (lane & 15));
    const uint32_t a_kofs = (uint32_t)((lane >> 4) * 16);
    const uint32_t b_row  = (uint32_t)(wn * 32 + (lane & 7) + ((lane & 16) >> 1));
    const uint32_t b_kofs = (uint32_t)((lane & 8) * 2);

    float acc[4][4][4];
    #pragma unroll
    for (int mf = 0; mf < 4; mf++)
        #pragma unroll
        for (int nf = 0; nf < 4; nf++)
            #pragma unroll
            for (int j = 0; j < 4; j++) acc[mf][nf][j] = 0.f;

    stage_load(sb + 0 * STG, Abase, Bhb, Blb, tid);
    CP_COMMIT();
    stage_load(sb + 1 * STG, Abase + TILE_K, Bhb + TILE_K, Blb + TILE_K, tid);
    CP_COMMIT();

    #pragma unroll 1
    for (int c = 0; c < CHUNKS; c++) {
        CP_WAIT1();
        __syncthreads();

        const uint32_t sbase = sb + (c & 1) * STG;
        #pragma unroll
        for (int ks = 0; ks < 4; ks++) {
            const uint32_t kb = (uint32_t)(ks * 32);
            uint32_t bhf[8], blf[8];
            #pragma unroll
            for (int nf2 = 0; nf2 < 2; nf2++) {
                uint32_t off = SMEM_SWIZZLE_128B(
                    (b_row + nf2 * 16) * 128 + kb + b_kofs);
                ldsm_x4(bhf[nf2*4+0], bhf[nf2*4+1], bhf[nf2*4+2], bhf[nf2*4+3],
                        sbase + OFF_BH + off);
                ldsm_x4(blf[nf2*4+0], blf[nf2*4+1], blf[nf2*4+2], blf[nf2*4+3],
                        sbase + OFF_BL + off);
            }
            #pragma unroll
            for (int mf = 0; mf < 4; mf++) {
                uint32_t aoff = SMEM_SWIZZLE_128B(
                    (a_row + mf * 16) * 128 + kb + a_kofs);
                uint32_t ah[4];
                ldsm_x4(ah[0], ah[1], ah[2], ah[3], sbase + OFF_A + aoff);
                #pragma unroll
                for (int nf = 0; nf < 4; nf++) {
                    mma_f16(acc[mf][nf], ah, &bhf[nf * 2]);
                    mma_f16(acc[mf][nf], ah, &blf[nf * 2]);
                }
            }
        }

        __syncthreads();
        if (c + 2 < CHUNKS)
            stage_load(sb + (c & 1) * STG, Abase + (c + 2) * TILE_K,
                       Bhb + (c + 2) * TILE_K, Blb + (c + 2) * TILE_K, tid);
        CP_COMMIT();
    }

    // ---- epilogue ----
    const int tq = lane >> 2;
    const int tr = lane & 3;
    float2 bv[4];
    #pragma unroll
    for (int nf = 0; nf < 4; nf++) {
        int col = bn + wn * 32 + nf * 8 + tr * 2;
        bv[nf].x = bias[col];
        bv[nf].y = bias[col + 1];
    }
    #pragma unroll
    for (int mf = 0; mf < 4; mf++) {
        #pragma unroll
        for (int half = 0; half < 2; half++) {
            int row = bm + wm * 64 + mf * 16 + tq + half * 8;
            float mv = (flags & 2) ? mask[row] : 1.0f;
            size_t rbase = (size_t)row * N + bn + wn * 32 + tr * 2;
            #pragma unroll
            for (int nf = 0; nf < 4; nf++) {
                float vx = acc[mf][nf][half * 2 + 0] + bv[nf].x;
                float vy = acc[mf][nf][half * 2 + 1] + bv[nf].y;
                if (flags & 1) { vx = fmaxf(vx, 0.f); vy = fmaxf(vy, 0.f); }
                vx *= mv; vy *= mv;
                if (op == 3) {
                    *(float2*)(outp + rbase + nf * 8) = make_float2(vx, vy);
                } else {
                    *(uint32_t*)(C16 + rbase + nf * 8) = pack_h2(vx, vy);
                }
            }
        }
    }
}

// ===========================================================================
// Combined-weight precompute -> fp16 hi/lo planes (+ combined bias)
// ===========================================================================
__global__ void __launch_bounds__(256)
comb_kernel(const float* __restrict__ Wq, const float* __restrict__ Wqf,
            const float* __restrict__ Wk, const float* __restrict__ Wkf,
            const float* __restrict__ bq, const float* __restrict__ bk)
{
    const int isk = blockIdx.z;
    const float* Wbig = isk ? Wk : Wq;
    const float* Wf   = isk ? Wkf : Wqf;
    __half* outh = isk ? g_Wkch : g_Wqch;
    __half* outl = isk ? g_Wkcl : g_Wqcl;
    const int h  = blockIdx.y;
    const int e0 = blockIdx.x * 128;

    __shared__ float Wfs[FDIM][HDIM + 1];
    __shared__ float Ws[16][128];

    const int tid = threadIdx.x;
    for (int idx = tid; idx < FDIM * HDIM; idx += 256)
        Wfs[idx >> 7][idx & 127] = Wf[idx];
    __syncthreads();

    if (blockIdx.x == 0 && tid < FDIM) {
        const float* b = isk ? bk : bq;
        float s = 0.f;
        for (int d = 0; d < HDIM; d++) s += Wfs[tid][d] * b[h * HDIM + d];
        (isk ? g_bkc : g_bqc)[h * FDIM + tid] = s;
    }

    const int f  = tid & 63;
    const int eg = tid >> 6;
    float acc[32];
    #pragma unroll
    for (int j = 0; j < 32; j++) acc[j] = 0.f;

    for (int d0 = 0; d0 < HDIM; d0 += 16) {
        __syncthreads();
        #pragma unroll
        for (int i = 0; i < 2; i++) {
            int idx = tid + 256 * i;
            int dd  = idx >> 5;
            int c4  = (idx & 31) * 4;
            *(float4*)&Ws[dd][c4] =
                *(const float4*)(Wbig + (size_t)(h * HDIM + d0 + dd) * HID + e0 + c4);
        }
        __syncthreads();
        #pragma unroll
        for (int dd = 0; dd < 16; dd++) {
            float wf = Wfs[f][d0 + dd];
            #pragma unroll
            for (int j = 0; j < 32; j++)
                acc[j] += wf * Ws[dd][eg * 32 + j];
        }
    }
    #pragma unroll
    for (int j = 0; j < 32; j++) {
        size_t idx = (size_t)(h * FDIM + f) * HID + e0 + eg * 32 + j;
        float v = acc[j];
        __half hb = __float2half_rn(v);
        outh[idx] = hb;
        outl[idx] = __float2half_rn(v - __half2float(hb));
    }
}

// ===========================================================================
// kv aggregation via mma: per (chunk, bh): kvpart[f,e] = sum_s k'[s,f] V[s,e]
// A = k'^T (trans-ldmatrix from [s][f] smem), B = V (trans from [s][e]).
// 128 threads (4 warps over e). Also accumulates kspart (k' column sums).
// ===========================================================================
__global__ void __launch_bounds__(128)
kv_mma_kernel()
{
    __shared__ __align__(16) char sm[2][6144];   // per stage: A 2KB, V0 2KB, V1 2KB

    const int tid  = threadIdx.x;
    const int lane = tid & 31;
    const int w    = tid >> 5;                   // 0..3  (e: 4 x 32)
    const int bh   = blockIdx.y;
    const int b    = bh >> 4, h = bh & 15;
    const int s0   = blockIdx.x * (SEQ / KVCH);  // 256 s per chunk

    const __half* kpb = g_kp16 + ((size_t)(b * SEQ + s0) * NHEADS + h) * FDIM;
    const __half* vb  = g_vo16 + (size_t)(b * SEQ + s0) * HID + h * HDIM;

    const uint32_t sA = smem_u32(sm[0]);
    // stage loader: 16 s-rows; A: 128 threads x 1 chunk; V: x 2 chunks
    auto load_stage = [&](int slot, int sc) {
        uint32_t base = sA + slot * 6144;
        {
            int r = tid >> 3, c = tid & 7;       // A: [16s][64f]
            cp16(base + SMEM_SWIZZLE_128B((uint32_t)(r * 128 + c * 16)),
                 kpb + (size_t)(sc * 16 + r) * (NHEADS * FDIM) + c * 8);
        }
        #pragma unroll
        for (int i = 0; i < 2; i++) {
            int idx = tid + 128 * i;             // V: [16s][128e] as 2 subtiles
            int r = idx >> 4, c = idx & 15;
            int sub = c >> 3, cc = c & 7;
            cp16(base + 2048 + sub * 2048 +
                     SMEM_SWIZZLE_128B((uint32_t)(r * 128 + cc * 16)),
                 vb + (size_t)(sc * 16 + r) * HID + c * 8);
        }
    };

    float acc[4][4][4];
    #pragma unroll
    for (int mf = 0; mf < 4; mf++)
        #pragma unroll
        for (int nf = 0; nf < 4; nf++)
            #pragma unroll
            for (int j = 0; j < 4; j++) acc[mf][nf][j] = 0.f;
    float ksacc = 0.f;

    // trans-ldmatrix lane address components
    const uint32_t a_kr = (uint32_t)((lane & 7) + ((lane & 16) >> 1));  // k row
    const uint32_t a_mo = (uint32_t)(((lane & 8) >> 3) * 8);            // f off
    const uint32_t b_kr = (uint32_t)(lane & 15);
    const uint32_t b_eo = (uint32_t)(((lane >> 4) & 1) * 8);

    load_stage(0, 0); CP_COMMIT();
    load_stage(1, 1); CP_COMMIT();

    #pragma unroll 1
    for (int sc = 0; sc < 16; sc++) {
        CP_WAIT1();
        __syncthreads();
        const uint32_t base = sA + (sc & 1) * 6144;

        if (tid < FDIM) {                        // k' column sums from A tile
            #pragma unroll
            for (int s = 0; s < 16; s++)
                ksacc += __half2float(*(const __half*)(
                    sm[sc & 1] + SMEM_SWIZZLE_128B((uint32_t)(s * 128 + tid * 2))));
        }

        uint32_t bf[8];
        #pragma unroll
        for (int nb = 0; nb < 2; nb++) {         // e blocks of 16 within warp's 32
            int eg = w * 32 + nb * 16;
            int sub = eg >> 6, ein = eg & 63;
            uint32_t off = 2048 + sub * 2048 + SMEM_SWIZZLE_128B(
                b_kr * 128 + (uint32_t)(ein + b_eo) * 2);
            ldsm_x4_t(bf[nb*4+0], bf[nb*4+1], bf[nb*4+2], bf[nb*4+3], base + off);
        }
        #pragma unroll
        for (int mf = 0; mf < 4; mf++) {
            uint32_t af[4];
            uint32_t aoff = SMEM_SWIZZLE_128B(
                a_kr * 128 + (uint32_t)(mf * 16 + a_mo) * 2);
            ldsm_x4_t(af[0], af[1], af[2], af[3], base + aoff);
            #pragma unroll
            for (int nf = 0; nf < 4; nf++)
                mma_f16(acc[mf][nf], af, &bf[nf * 2]);
        }

        __syncthreads();
        if (sc + 2 < 16) load_stage(sc & 1, sc + 2);
        CP_COMMIT();
    }

    const int tq = lane >> 2, tr = lane & 3;
    float* dst = g_kvpart + ((size_t)blockIdx.x * BHEADS + bh) * FDIM * HDIM;
    #pragma unroll
    for (int mf = 0; mf < 4; mf++)
        #pragma unroll
        for (int half = 0; half < 2; half++) {
            int f = mf * 16 + tq + half * 8;
            #pragma unroll
            for (int nf = 0; nf < 4; nf++) {
                int e = w * 32 + nf * 8 + tr * 2;
                *(float2*)(dst + f * HDIM + e) = make_float2(
                    acc[mf][nf][half * 2 + 0], acc[mf][nf][half * 2 + 1]);
            }
        }
    if (tid < FDIM)
        g_kspart[(blockIdx.x * BHEADS + bh) * FDIM + tid] = ksacc;
}

// ===========================================================================
// kv reduce + transpose -> fp16 kv16T[bh][e][f]
// ===========================================================================
__global__ void __launch_bounds__(256)
kv_reduce_kernel()
{
    __shared__ float smt[FDIM][HDIM + 1];
    const int tid = threadIdx.x;
    const int bh  = blockIdx.x;
    #pragma unroll 4
    for (int k = 0; k < 32; k++) {
        int idx = tid + 256 * k;                 // [f][e]
        float s = 0.f;
        #pragma unroll
        for (int c = 0; c < KVCH; c++)
            s += g_kvpart[((size_t)c * BHEADS + bh) * FDIM * HDIM + idx];
        smt[idx >> 7][idx & 127] = s;
    }
    __syncthreads();
    __half* dst = g_kv16T + (size_t)bh * HDIM * FDIM;
    #pragma unroll 4
    for (int k = 0; k < 32; k++) {
        int o = tid + 256 * k;                   // [e][f]
        dst[o] = __float2half_rn(smt[o & 63][o >> 6]);
    }
}

__global__ void __launch_bounds__(256)
ksum_reduce_kernel()
{
    int i = blockIdx.x * 256 + threadIdx.x;
    float s = 0.f;
    #pragma unroll
    for (int c = 0; c < KVCH; c++) s += g_kspart[c * BHEADS * FDIM + i];
    g_ksum[i] = s;
}

// ===========================================================================
// qkv via mma: per (128 rows, head): A = q'16 [128r x 64f], B = kv16T [128e x 64f]
// fp32 denominators SIMT; output /den packed fp16 -> g_a16. 256 threads.
// ===========================================================================
__global__ void __launch_bounds__(256)
qkv_mma_kernel()
{
    __shared__ __align__(16) char smq[16384];    // [128r][64f] swizzled
    __shared__ __align__(16) char smk[16384];    // [128e][64f] swizzled
    __shared__ float sks[FDIM];
    __shared__ float sinv[128];

    const int tid  = threadIdx.x;
    const int lane = tid & 31;
    const int wid  = tid >> 5;
    const int wm   = wid >> 2;                   // 0..1 (rows: 2 x 64)
    const int wn   = wid & 3;                    // 0..3 (e: 4 x 32)
    const int h    = blockIdx.y;
    const int bs0  = blockIdx.x * 128;
    const int b    = bs0 / SEQ;
    const int bh   = b * NHEADS + h;

    const uint32_t sq = smem_u32(smq);
    const uint32_t sk = smem_u32(smk);

    #pragma unroll
    for (int i = 0; i < 4; i++) {
        int idx = tid + 256 * i;                 // 1024 chunks each
        int r = idx >> 3, c = idx & 7;
        uint32_t off = SMEM_SWIZZLE_128B((uint32_t)(r * 128 + c * 16));
        cp16(sq + off, g_qp16 + ((size_t)(bs0 + r) * NHEADS + h) * FDIM + c * 8);
        cp16(sk + off, g_kv16T + ((size_t)bh * HDIM + r) * FDIM + c * 8);
    }
    if (tid < FDIM) sks[tid] = g_ksum[bh * FDIM + tid];
    CP_COMMIT();
    CP_WAIT0();
    __syncthreads();

    if (tid < 128) {                             // denominators
        float d = 0.f;
        #pragma unroll 8
        for (int f = 0; f < FDIM; f++)
            d += __half2float(*(const __half*)(
                     smq + SMEM_SWIZZLE_128B((uint32_t)(tid * 128 + f * 2)))) *
                 sks[f];
        sinv[tid] = 1.0f / (d + 1e-8f);
    }
    __syncthreads();

    const uint32_t a_row  = (uint32_t)(wm * 64 + (lane & 15));
    const uint32_t a_kofs = (uint32_t)((lane >> 4) * 16);
    const uint32_t b_row  = (uint32_t)(wn * 32 + (lane & 7) + ((lane & 16) >> 1));
    const uint32_t b_kofs = (uint32_t)((lane & 8) * 2);

    float acc[4][4][4];
    #pragma unroll
    for (int mf = 0; mf < 4; mf++)
        #pragma unroll
        for (int nf = 0; nf < 4; nf++)
            #pragma unroll
            for (int j = 0; j < 4; j++) acc[mf][nf][j] = 0.f;

    #pragma unroll
    for (int ks = 0; ks < 4; ks++) {
        const uint32_t kb = (uint32_t)(ks * 32);
        uint32_t bf[8];
        #pragma unroll
        for (int nf2 = 0; nf2 < 2; nf2++) {
            uint32_t off = SMEM_SWIZZLE_128B(
                (b_row + nf2 * 16) * 128 + kb + b_kofs);
            ldsm_x4(bf[nf2*4+0], bf[nf2*4+1], bf[nf2*4+2], bf[nf2*4+3], sk + off);
        }
        #pragma unroll
        for (int mf = 0; mf < 4; mf++) {
            uint32_t af[4];
            uint32_t aoff = SMEM_SWIZZLE_128B(
                (a_row + mf * 16) * 128 + kb + a_kofs);
            ldsm_x4(af[0], af[1], af[2], af[3], sq + aoff);
            #pragma unroll
            for (int nf = 0; nf < 4; nf++)
                mma_f16(acc[mf][nf], af, &bf[nf * 2]);
        }
    }

    const int tq = lane >> 2, tr = lane & 3;
    #pragma unroll
    for (int mf = 0; mf < 4; mf++)
        #pragma unroll
        for (int half = 0; half < 2; half++) {
            int m = wm * 64 + mf * 16 + tq + half * 8;
            float inv = sinv[m];
            size_t rbase = (size_t)(bs0 + m) * HID + h * HDIM + wn * 32 + tr * 2;
            #pragma unroll
            for (int nf = 0; nf < 4; nf++) {
                *(uint32_t*)(g_a16 + rbase + nf * 8) = pack_h2(
                    acc[mf][nf][half * 2 + 0] * inv,
                    acc[mf][nf][half * 2 + 1] * inv);
            }
        }
}

// ===========================================================================
extern "C" void kernel_launch(void* const* d_in, const int* in_sizes, int n_in,
                              void* d_out, int out_size)
{
    const float* query = (const float*)d_in[0];
    const float* key_  = (const float*)d_in[1];
    const float* value = (const float*)d_in[2];
    const float* mask  = (const float*)d_in[3];
    const float* Wq    = (const float*)d_in[4];
    const float* bq    = (const float*)d_in[5];
    const float* Wk    = (const float*)d_in[6];
    const float* bk    = (const float*)d_in[7];
    const float* Wv    = (const float*)d_in[8];
    const float* bv    = (const float*)d_in[9];
    const float* Wqf   = (const float*)d_in[10];
    const float* Wkf   = (const float*)d_in[11];
    const float* Wo    = (const float*)d_in[12];
    const float* bo    = (const float*)d_in[13];
    float* out = (float*)d_out;

    cudaFuncSetAttribute(gemm_tc, cudaFuncAttributeMaxDynamicSharedMemorySize, GSMEM);

    const int nbig = (MROWS * HID) / 8;      // 4194304
    const int nw   = (HID * HID) / 8;        // 524288

    comb_kernel<<<dim3(HID / 128, NHEADS, 2), 256>>>(Wq, Wqf, Wk, Wkf, bq, bk);   // 0
    conv3_kernel<<<dim3((nbig + 255) / 256, 3), 256>>>(query, key_, value, nbig); // 1
    convw_kernel<<<(nw + 255) / 256, 256>>>(Wv, 0, nw);                           // 2
    // merged q' / k' / V GEMMs (fp16 outputs)
    gemm_tc<<<4096, 256, GSMEM>>>(0, bv, nullptr, nullptr, mask);                 // 3
    convw_kernel<<<(nw + 255) / 256, 256>>>(Wo, 1, nw);                           // 4

    kv_mma_kernel<<<dim3(KVCH, BHEADS), 128>>>();                                 // 5
    kv_reduce_kernel<<<BHEADS, 256>>>();                                          // 6
    ksum_reduce_kernel<<<(BHEADS * FDIM) / 256, 256>>>();                         // 7
    qkv_mma_kernel<<<dim3(MROWS / 128, NHEADS), 256>>>();                         // 8

    // out = attn @ Wo^T + bo
    gemm_tc<<<2048, 256, GSMEM>>>(1, nullptr, bo, out, mask);                     // 9
}

// round 13
// speedup vs baseline: 3.3800x; 1.6068x over previous
#include <cuda_runtime.h>
#include <cuda_fp16.h>
#include <cstdint>

// Problem constants (fixed by the dataset)
#define BATCH   4
#define SEQ     4096
#define HID     2048
#define NHEADS  16
#define HDIM    128
#define FDIM    64
#define MROWS   (BATCH * SEQ)          // 16384
#define M2      (MROWS * NHEADS)       // 262144
#define BHEADS  (BATCH * NHEADS)       // 64
#define KVCH    16
#define KVELEM  (BHEADS * FDIM * HDIM) // 524288
#define NQP     (NHEADS * FDIM)        // 1024

// ---------------- scratch (static device globals; no allocation) -----------
__device__ float g_kvpart[(size_t)KVCH * KVELEM];
__device__ float g_kspart[KVCH * BHEADS * FDIM];
__device__ float g_ksum[BHEADS * FDIM];
__device__ float g_bqc[NQP];
__device__ float g_bkc[NQP];
// fp16 activations (GEMM inputs)
__device__ __half g_q16[(size_t)MROWS * HID];
__device__ __half g_k16[(size_t)MROWS * HID];
__device__ __half g_v16[(size_t)MROWS * HID];
__device__ __half g_a16[(size_t)MROWS * HID];
// fp16 GEMM outputs
__device__ __half g_qp16[(size_t)M2 * FDIM];
__device__ __half g_kp16[(size_t)M2 * FDIM];
__device__ __half g_vo16[(size_t)MROWS * HID];
__device__ __half g_kv16T[(size_t)BHEADS * HDIM * FDIM];   // [bh][e][f]
// fp16 weight planes (single precision level — error model has margin)
__device__ __half g_Wv16[(size_t)HID * HID];
__device__ __half g_Wo16[(size_t)HID * HID];
__device__ __half g_Wqc16[(size_t)NQP * HID];
__device__ __half g_Wkc16[(size_t)NQP * HID];

// =========================== helpers =======================================
__device__ __forceinline__ uint32_t smem_u32(const void* p) {
    uint32_t a;
    asm("{ .reg .u64 t; cvta.to.shared.u64 t, %1; cvt.u32.u64 %0, t; }"
        : "=r"(a) : "l"(p));
    return a;
}
#define SMEM_SWIZZLE_128B(off) ((off) ^ (((off) >> 3) & 0x70))

__device__ __forceinline__ void cp16(uint32_t dst, const void* src) {
    asm volatile("cp.async.cg.shared.global [%0], [%1], 16;"
                 :: "r"(dst), "l"(src) : "memory");
}
#define CP_COMMIT() asm volatile("cp.async.commit_group;" ::: "memory")
#define CP_WAIT1()  asm volatile("cp.async.wait_group 1;" ::: "memory")
#define CP_WAIT0()  asm volatile("cp.async.wait_group 0;" ::: "memory")

__device__ __forceinline__ void ldsm_x4(uint32_t& r0, uint32_t& r1,
                                        uint32_t& r2, uint32_t& r3,
                                        uint32_t addr) {
    asm volatile("ldmatrix.sync.aligned.m8n8.x4.shared.b16 {%0,%1,%2,%3}, [%4];"
                 : "=r"(r0), "=r"(r1), "=r"(r2), "=r"(r3) : "r"(addr));
}
__device__ __forceinline__ void ldsm_x4_t(uint32_t& r0, uint32_t& r1,
                                          uint32_t& r2, uint32_t& r3,
                                          uint32_t addr) {
    asm volatile("ldmatrix.sync.aligned.m8n8.x4.trans.shared.b16 {%0,%1,%2,%3}, [%4];"
                 : "=r"(r0), "=r"(r1), "=r"(r2), "=r"(r3) : "r"(addr));
}
__device__ __forceinline__ void mma_f16(float* d, const uint32_t* a,
                                        const uint32_t* b) {
    asm volatile(
        "mma.sync.aligned.m16n8k16.row.col.f32.f16.f16.f32 "
        "{%0,%1,%2,%3}, {%4,%5,%6,%7}, {%8,%9}, {%0,%1,%2,%3};"
        : "+f"(d[0]), "+f"(d[1]), "+f"(d[2]), "+f"(d[3])
        : "r"(a[0]), "r"(a[1]), "r"(a[2]), "r"(a[3]), "r"(b[0]), "r"(b[1]));
}
__device__ __forceinline__ uint32_t pack_h2(float x, float y) {
    __half2 h = __floats2half2_rn(x, y);
    return *reinterpret_cast<uint32_t*>(&h);
}

// ===========================================================================
// fp32 -> fp16 conversions
// ===========================================================================
__global__ void __launch_bounds__(256)
conv3_kernel(const float* __restrict__ q, const float* __restrict__ k,
             const float* __restrict__ v, int n8)
{
    const int sel = blockIdx.y;
    const float* src = (sel == 0) ? q : (sel == 1) ? k : v;
    __half* dst = (sel == 0) ? g_q16 : (sel == 1) ? g_k16 : g_v16;
    int i = blockIdx.x * 256 + threadIdx.x;
    if (i >= n8) return;
    const float4* s4 = (const float4*)src + (size_t)i * 2;
    float4 v0 = s4[0], v1 = s4[1];
    uint4 p;
    p.x = pack_h2(v0.x, v0.y);
    p.y = pack_h2(v0.z, v0.w);
    p.z = pack_h2(v1.x, v1.y);
    p.w = pack_h2(v1.z, v1.w);
    *(uint4*)(dst + (size_t)i * 8) = p;
}

__global__ void __launch_bounds__(256)
convw_kernel(const float* __restrict__ wv, const float* __restrict__ wo, int n8)
{
    const int sel = blockIdx.y;
    const float* src = sel ? wo : wv;
    __half* dst = sel ? g_Wo16 : g_Wv16;
    int i = blockIdx.x * 256 + threadIdx.x;
    if (i >= n8) return;
    const float4* s4 = (const float4*)src + (size_t)i * 2;
    float4 v0 = s4[0], v1 = s4[1];
    uint4 p;
    p.x = pack_h2(v0.x, v0.y);
    p.y = pack_h2(v0.z, v0.w);
    p.z = pack_h2(v1.x, v1.y);
    p.w = pack_h2(v1.z, v1.w);
    *(uint4*)(dst + (size_t)i * 8) = p;
}

// ===========================================================================
// Main tensor-core GEMM (fp16 A, fp16 W single plane, 1 MMA pass).
// 128x128 tile, TILE_K=64, cp.async 3-stage single-barrier pipeline,
// 256 threads, 2 CTA/SM (96KB smem/CTA).
// mode 0: merged q'/k'/V (grid 4096, fp16 outputs); mode 1: O (2048, fp32 out)
// ===========================================================================
#define TILE_K   64
#define CHUNKS   (HID / TILE_K)   // 32
#define OFF_A    0
#define OFF_B    16384
#define STG      32768            // A 16KB + B 16KB
#define NSTAGE   3
#define GSMEM    (NSTAGE * STG)   // 98304

__device__ __forceinline__ void stage_load(
    uint32_t sbuf, const __half* pa, const __half* pb, int tid)
{
    #pragma unroll
    for (int i = 0; i < 4; i++) {
        int idx = tid + 256 * i;          // 0..1023
        int r   = idx >> 3;               // 0..127
        int q   = idx & 7;
        uint32_t off = SMEM_SWIZZLE_128B((uint32_t)(r * 128 + q * 16));
        size_t g = (size_t)r * HID + q * 8;
        cp16(sbuf + OFF_A + off, pa + g);
        cp16(sbuf + OFF_B + off, pb + g);
    }
}

__global__ void __launch_bounds__(256, 2)
gemm_tc(int mode, const float* __restrict__ bvv, const float* __restrict__ boo,
        float* __restrict__ outp, const float* __restrict__ mask)
{
    extern __shared__ char smem[];

    int op, bx, by;
    if (mode == 0) {
        int b = blockIdx.x;
        if (b < 1024)      { op = 0; bx = b & 7; by = b >> 3; }
        else if (b < 2048) { b -= 1024; op = 1; bx = b & 7; by = b >> 3; }
        else               { b -= 2048; op = 2; bx = b & 15; by = b >> 4; }
    } else {
        int b = blockIdx.x;  op = 3; bx = b & 15; by = b >> 4;
    }
    const __half *A16, *W16;
    const float* bias;
    __half* C16 = nullptr;
    int N, flags;
    switch (op) {
        case 0: A16 = g_q16; W16 = g_Wqc16;
                bias = g_bqc; C16 = g_qp16; N = NQP; flags = 1; break;
        case 1: A16 = g_k16; W16 = g_Wkc16;
                bias = g_bkc; C16 = g_kp16; N = NQP; flags = 3; break;
        case 2: A16 = g_v16; W16 = g_Wv16;
                bias = bvv; C16 = g_vo16; N = HID; flags = 0; break;
        default: A16 = g_a16; W16 = g_Wo16;
                bias = boo; N = HID; flags = 0; break;
    }
    const int bn = bx * 128;
    const int bm = by * 128;

    const uint32_t sb = smem_u32(smem);
    const int tid  = threadIdx.x;
    const int lane = tid & 31;
    const int wid  = tid >> 5;
    const int wm   = wid >> 2;
    const int wn   = wid & 3;

    const __half* Abase = A16 + (size_t)bm * HID;
    const __half* Bbase = W16 + (size_t)bn * HID;

    const uint32_t a_row  = (uint32_t)(wm * 64 + (lane & 15));
    const uint32_t a_kofs = (uint32_t)((lane >> 4) * 16);
    const uint32_t b_row  = (uint32_t)(wn * 32 + (lane & 7) + ((lane & 16) >> 1));
    const uint32_t b_kofs = (uint32_t)((lane & 8) * 2);

    float acc[4][4][4];
    #pragma unroll
    for (int mf = 0; mf < 4; mf++)
        #pragma unroll
        for (int nf = 0; nf < 4; nf++)
            #pragma unroll
            for (int j = 0; j < 4; j++) acc[mf][nf][j] = 0.f;

    // prologue: stages 0,1
    stage_load(sb + 0 * STG, Abase, Bbase, tid);
    CP_COMMIT();
    stage_load(sb + 1 * STG, Abase + TILE_K, Bbase + TILE_K, tid);
    CP_COMMIT();

    #pragma unroll 1
    for (int c = 0; c < CHUNKS; c++) {
        CP_WAIT1();            // my stage-c loads done (only c+1 may pend)
        __syncthreads();       // all threads' stage-c loads done; all readers
                               // of stage c-1 (slot (c+2)%3) have passed

        if (c + 2 < CHUNKS)
            stage_load(sb + ((c + 2) % NSTAGE) * STG,
                       Abase + (c + 2) * TILE_K, Bbase + (c + 2) * TILE_K, tid);
        CP_COMMIT();           // empty commits are legal no-ops

        const uint32_t sbase = sb + (c % NSTAGE) * STG;
        #pragma unroll
        for (int ks = 0; ks < 4; ks++) {
            const uint32_t kb = (uint32_t)(ks * 32);
            uint32_t bf[8];
            #pragma unroll
            for (int nf2 = 0; nf2 < 2; nf2++) {
                uint32_t off = SMEM_SWIZZLE_128B(
                    (b_row + nf2 * 16) * 128 + kb + b_kofs);
                ldsm_x4(bf[nf2*4+0], bf[nf2*4+1], bf[nf2*4+2], bf[nf2*4+3],
                        sbase + OFF_B + off);
            }
            #pragma unroll
            for (int mf = 0; mf < 4; mf++) {
                uint32_t aoff = SMEM_SWIZZLE_128B(
                    (a_row + mf * 16) * 128 + kb + a_kofs);
                uint32_t ah[4];
                ldsm_x4(ah[0], ah[1], ah[2], ah[3], sbase + OFF_A + aoff);
                #pragma unroll
                for (int nf = 0; nf < 4; nf++)
                    mma_f16(acc[mf][nf], ah, &bf[nf * 2]);
            }
        }
    }

    // ---- epilogue ----
    const int tq = lane >> 2;
    const int tr = lane & 3;
    float2 bv[4];
    #pragma unroll
    for (int nf = 0; nf < 4; nf++) {
        int col = bn + wn * 32 + nf * 8 + tr * 2;
        bv[nf].x = bias[col];
        bv[nf].y = bias[col + 1];
    }
    #pragma unroll
    for (int mf = 0; mf < 4; mf++) {
        #pragma unroll
        for (int half = 0; half < 2; half++) {
            int row = bm + wm * 64 + mf * 16 + tq + half * 8;
            float mv = (flags & 2) ? mask[row] : 1.0f;
            size_t rbase = (size_t)row * N + bn + wn * 32 + tr * 2;
            #pragma unroll
            for (int nf = 0; nf < 4; nf++) {
                float vx = acc[mf][nf][half * 2 + 0] + bv[nf].x;
                float vy = acc[mf][nf][half * 2 + 1] + bv[nf].y;
                if (flags & 1) { vx = fmaxf(vx, 0.f); vy = fmaxf(vy, 0.f); }
                vx *= mv; vy *= mv;
                if (op == 3) {
                    *(float2*)(outp + rbase + nf * 8) = make_float2(vx, vy);
                } else {
                    *(uint32_t*)(C16 + rbase + nf * 8) = pack_h2(vx, vy);
                }
            }
        }
    }
}

// ===========================================================================
// Combined-weight precompute -> single fp16 plane (+ combined bias)
// ===========================================================================
__global__ void __launch_bounds__(256)
comb_kernel(const float* __restrict__ Wq, const float* __restrict__ Wqf,
            const float* __restrict__ Wk, const float* __restrict__ Wkf,
            const float* __restrict__ bq, const float* __restrict__ bk)
{
    const int isk = blockIdx.z;
    const float* Wbig = isk ? Wk : Wq;
    const float* Wf   = isk ? Wkf : Wqf;
    __half* out = isk ? g_Wkc16 : g_Wqc16;
    const int h  = blockIdx.y;
    const int e0 = blockIdx.x * 128;

    __shared__ float Wfs[FDIM][HDIM + 1];
    __shared__ float Ws[16][128];

    const int tid = threadIdx.x;
    for (int idx = tid; idx < FDIM * HDIM; idx += 256)
        Wfs[idx >> 7][idx & 127] = Wf[idx];
    __syncthreads();

    if (blockIdx.x == 0 && tid < FDIM) {
        const float* b = isk ? bk : bq;
        float s = 0.f;
        for (int d = 0; d < HDIM; d++) s += Wfs[tid][d] * b[h * HDIM + d];
        (isk ? g_bkc : g_bqc)[h * FDIM + tid] = s;
    }

    const int f  = tid & 63;
    const int eg = tid >> 6;
    float acc[32];
    #pragma unroll
    for (int j = 0; j < 32; j++) acc[j] = 0.f;

    for (int d0 = 0; d0 < HDIM; d0 += 16) {
        __syncthreads();
        #pragma unroll
        for (int i = 0; i < 2; i++) {
            int idx = tid + 256 * i;
            int dd  = idx >> 5;
            int c4  = (idx & 31) * 4;
            *(float4*)&Ws[dd][c4] =
                *(const float4*)(Wbig + (size_t)(h * HDIM + d0 + dd) * HID + e0 + c4);
        }
        __syncthreads();
        #pragma unroll
        for (int dd = 0; dd < 16; dd++) {
            float wf = Wfs[f][d0 + dd];
            #pragma unroll
            for (int j = 0; j < 32; j++)
                acc[j] += wf * Ws[dd][eg * 32 + j];
        }
    }
    #pragma unroll
    for (int j = 0; j < 32; j++) {
        size_t idx = (size_t)(h * FDIM + f) * HID + e0 + eg * 32 + j;
        out[idx] = __float2half_rn(acc[j]);
    }
}

// ===========================================================================
// kv aggregation via mma: per (chunk, bh): kvpart[f,e] = sum_s k'[s,f] V[s,e]
// A = k'^T (trans-ldmatrix from [s][f] smem), B = V (trans from [s][e]).
// 128 threads (4 warps over e). Also accumulates kspart (k' column sums).
// ===========================================================================
__global__ void __launch_bounds__(128)
kv_mma_kernel()
{
    __shared__ __align__(16) char sm[2][6144];   // per stage: A 2KB, V0 2KB, V1 2KB

    const int tid  = threadIdx.x;
    const int lane = tid & 31;
    const int w    = tid >> 5;                   // 0..3  (e: 4 x 32)
    const int bh   = blockIdx.y;
    const int b    = bh >> 4, h = bh & 15;
    const int s0   = blockIdx.x * (SEQ / KVCH);  // 256 s per chunk

    const __half* kpb = g_kp16 + ((size_t)(b * SEQ + s0) * NHEADS + h) * FDIM;
    const __half* vb  = g_vo16 + (size_t)(b * SEQ + s0) * HID + h * HDIM;

    const uint32_t sA = smem_u32(sm[0]);
    auto load_stage = [&](int slot, int sc) {
        uint32_t base = sA + slot * 6144;
        {
            int r = tid >> 3, c = tid & 7;       // A: [16s][64f]
            cp16(base + SMEM_SWIZZLE_128B((uint32_t)(r * 128 + c * 16)),
                 kpb + (size_t)(sc * 16 + r) * (NHEADS * FDIM) + c * 8);
        }
        #pragma unroll
        for (int i = 0; i < 2; i++) {
            int idx = tid + 128 * i;             // V: [16s][128e] as 2 subtiles
            int r = idx >> 4, c = idx & 15;
            int sub = c >> 3, cc = c & 7;
            cp16(base + 2048 + sub * 2048 +
                     SMEM_SWIZZLE_128B((uint32_t)(r * 128 + cc * 16)),
                 vb + (size_t)(sc * 16 + r) * HID + c * 8);
        }
    };

    float acc[4][4][4];
    #pragma unroll
    for (int mf = 0; mf < 4; mf++)
        #pragma unroll
        for (int nf = 0; nf < 4; nf++)
            #pragma unroll
            for (int j = 0; j < 4; j++) acc[mf][nf][j] = 0.f;
    float ksacc = 0.f;

    const uint32_t a_kr = (uint32_t)((lane & 7) + ((lane & 16) >> 1));
    const uint32_t a_mo = (uint32_t)(((lane & 8) >> 3) * 8);
    const uint32_t b_kr = (uint32_t)(lane & 15);
    const uint32_t b_eo = (uint32_t)(((lane >> 4) & 1) * 8);

    load_stage(0, 0); CP_COMMIT();
    load_stage(1, 1); CP_COMMIT();

    #pragma unroll 1
    for (int sc = 0; sc < 16; sc++) {
        CP_WAIT1();
        __syncthreads();
        const uint32_t base = sA + (sc & 1) * 6144;

        if (tid < FDIM) {
            #pragma unroll
            for (int s = 0; s < 16; s++)
                ksacc += __half2float(*(const __half*)(
                    sm[sc & 1] + SMEM_SWIZZLE_128B((uint32_t)(s * 128 + tid * 2))));
        }

        uint32_t bf[8];
        #pragma unroll
        for (int nb = 0; nb < 2; nb++) {
            int eg = w * 32 + nb * 16;
            int sub = eg >> 6, ein = eg & 63;
            uint32_t off = 2048 + sub * 2048 + SMEM_SWIZZLE_128B(
                b_kr * 128 + (uint32_t)(ein + b_eo) * 2);
            ldsm_x4_t(bf[nb*4+0], bf[nb*4+1], bf[nb*4+2], bf[nb*4+3], base + off);
        }
        #pragma unroll
        for (int mf = 0; mf < 4; mf++) {
            uint32_t af[4];
            uint32_t aoff = SMEM_SWIZZLE_128B(
                a_kr * 128 + (uint32_t)(mf * 16 + a_mo) * 2);
            ldsm_x4_t(af[0], af[1], af[2], af[3], base + aoff);
            #pragma unroll
            for (int nf = 0; nf < 4; nf++)
                mma_f16(acc[mf][nf], af, &bf[nf * 2]);
        }

        __syncthreads();
        if (sc + 2 < 16) load_stage(sc & 1, sc + 2);
        CP_COMMIT();
    }

    const int tq = lane >> 2, tr = lane & 3;
    float* dst = g_kvpart + ((size_t)blockIdx.x * BHEADS + bh) * FDIM * HDIM;
    #pragma unroll
    for (int mf = 0; mf < 4; mf++)
        #pragma unroll
        for (int half = 0; half < 2; half++) {
            int f = mf * 16 + tq + half * 8;
            #pragma unroll
            for (int nf = 0; nf < 4; nf++) {
                int e = w * 32 + nf * 8 + tr * 2;
                *(float2*)(dst + f * HDIM + e) = make_float2(
                    acc[mf][nf][half * 2 + 0], acc[mf][nf][half * 2 + 1]);
            }
        }
    if (tid < FDIM)
        g_kspart[(blockIdx.x * BHEADS + bh) * FDIM + tid] = ksacc;
}

// ===========================================================================
// kv reduce + transpose -> fp16 kv16T[bh][e][f]
// ===========================================================================
__global__ void __launch_bounds__(256)
kv_reduce_kernel()
{
    __shared__ float smt[FDIM][HDIM + 1];
    const int tid = threadIdx.x;
    const int bh  = blockIdx.x;
    #pragma unroll 4
    for (int k = 0; k < 32; k++) {
        int idx = tid + 256 * k;                 // [f][e]
        float s = 0.f;
        #pragma unroll
        for (int c = 0; c < KVCH; c++)
            s += g_kvpart[((size_t)c * BHEADS + bh) * FDIM * HDIM + idx];
        smt[idx >> 7][idx & 127] = s;
    }
    __syncthreads();
    __half* dst = g_kv16T + (size_t)bh * HDIM * FDIM;
    #pragma unroll 4
    for (int k = 0; k < 32; k++) {
        int o = tid + 256 * k;                   // [e][f]
        dst[o] = __float2half_rn(smt[o & 63][o >> 6]);
    }
}

__global__ void __launch_bounds__(256)
ksum_reduce_kernel()
{
    int i = blockIdx.x * 256 + threadIdx.x;
    float s = 0.f;
    #pragma unroll
    for (int c = 0; c < KVCH; c++) s += g_kspart[c * BHEADS * FDIM + i];
    g_ksum[i] = s;
}

// ===========================================================================
// qkv via mma: per (128 rows, head): A = q'16 [128r x 64f], B = kv16T [128e x 64f]
// fp32 denominators SIMT; output /den packed fp16 -> g_a16. 256 threads.
// ===========================================================================
__global__ void __launch_bounds__(256)
qkv_mma_kernel()
{
    __shared__ __align__(16) char smq[16384];    // [128r][64f] swizzled
    __shared__ __align__(16) char smk[16384];    // [128e][64f] swizzled
    __shared__ float sks[FDIM];
    __shared__ float sinv[128];

    const int tid  = threadIdx.x;
    const int lane = tid & 31;
    const int wid  = tid >> 5;
    const int wm   = wid >> 2;
    const int wn   = wid & 3;
    const int h    = blockIdx.y;
    const int bs0  = blockIdx.x * 128;
    const int b    = bs0 / SEQ;
    const int bh   = b * NHEADS + h;

    const uint32_t sq = smem_u32(smq);
    const uint32_t sk = smem_u32(smk);

    #pragma unroll
    for (int i = 0; i < 4; i++) {
        int idx = tid + 256 * i;
        int r = idx >> 3, c = idx & 7;
        uint32_t off = SMEM_SWIZZLE_128B((uint32_t)(r * 128 + c * 16));
        cp16(sq + off, g_qp16 + ((size_t)(bs0 + r) * NHEADS + h) * FDIM + c * 8);
        cp16(sk + off, g_kv16T + ((size_t)bh * HDIM + r) * FDIM + c * 8);
    }
    if (tid < FDIM) sks[tid] = g_ksum[bh * FDIM + tid];
    CP_COMMIT();
    CP_WAIT0();
    __syncthreads();

    if (tid < 128) {
        float d = 0.f;
        #pragma unroll 8
        for (int f = 0; f < FDIM; f++)
            d += __half2float(*(const __half*)(
                     smq + SMEM_SWIZZLE_128B((uint32_t)(tid * 128 + f * 2)))) *
                 sks[f];
        sinv[tid] = 1.0f / (d + 1e-8f);
    }
    __syncthreads();

    const uint32_t a_row  = (uint32_t)(wm * 64 + (lane & 15));
    const uint32_t a_kofs = (uint32_t)((lane >> 4) * 16);
    const uint32_t b_row  = (uint32_t)(wn * 32 + (lane & 7) + ((lane & 16) >> 1));
    const uint32_t b_kofs = (uint32_t)((lane & 8) * 2);

    float acc[4][4][4];
    #pragma unroll
    for (int mf = 0; mf < 4; mf++)
        #pragma unroll
        for (int nf = 0; nf < 4; nf++)
            #pragma unroll
            for (int j = 0; j < 4; j++) acc[mf][nf][j] = 0.f;

    #pragma unroll
    for (int ks = 0; ks < 4; ks++) {
        const uint32_t kb = (uint32_t)(ks * 32);
        uint32_t bf[8];
        #pragma unroll
        for (int nf2 = 0; nf2 < 2; nf2++) {
            uint32_t off = SMEM_SWIZZLE_128B(
                (b_row + nf2 * 16) * 128 + kb + b_kofs);
            ldsm_x4(bf[nf2*4+0], bf[nf2*4+1], bf[nf2*4+2], bf[nf2*4+3], sk + off);
        }
        #pragma unroll
        for (int mf = 0; mf < 4; mf++) {
            uint32_t af[4];
            uint32_t aoff = SMEM_SWIZZLE_128B(
                (a_row + mf * 16) * 128 + kb + a_kofs);
            ldsm_x4(af[0], af[1], af[2], af[3], sq + aoff);
            #pragma unroll
            for (int nf = 0; nf < 4; nf++)
                mma_f16(acc[mf][nf], af, &bf[nf * 2]);
        }
    }

    const int tq = lane >> 2, tr = lane & 3;
    #pragma unroll
    for (int mf = 0; mf < 4; mf++)
        #pragma unroll
        for (int half = 0; half < 2; half++) {
            int m = wm * 64 + mf * 16 + tq + half * 8;
            float inv = sinv[m];
            size_t rbase = (size_t)(bs0 + m) * HID + h * HDIM + wn * 32 + tr * 2;
            #pragma unroll
            for (int nf = 0; nf < 4; nf++) {
                *(uint32_t*)(g_a16 + rbase + nf * 8) = pack_h2(
                    acc[mf][nf][half * 2 + 0] * inv,
                    acc[mf][nf][half * 2 + 1] * inv);
            }
        }
}

// ===========================================================================
extern "C" void kernel_launch(void* const* d_in, const int* in_sizes, int n_in,
                              void* d_out, int out_size)
{
    const float* query = (const float*)d_in[0];
    const float* key_  = (const float*)d_in[1];
    const float* value = (const float*)d_in[2];
    const float* mask  = (const float*)d_in[3];
    const float* Wq    = (const float*)d_in[4];
    const float* bq    = (const float*)d_in[5];
    const float* Wk    = (const float*)d_in[6];
    const float* bk    = (const float*)d_in[7];
    const float* Wv    = (const float*)d_in[8];
    const float* bv    = (const float*)d_in[9];
    const float* Wqf   = (const float*)d_in[10];
    const float* Wkf   = (const float*)d_in[11];
    const float* Wo    = (const float*)d_in[12];
    const float* bo    = (const float*)d_in[13];
    float* out = (float*)d_out;

    cudaFuncSetAttribute(gemm_tc, cudaFuncAttributeMaxDynamicSharedMemorySize, GSMEM);

    const int nbig = (MROWS * HID) / 8;      // 4194304
    const int nw   = (HID * HID) / 8;        // 524288

    comb_kernel<<<dim3(HID / 128, NHEADS, 2), 256>>>(Wq, Wqf, Wk, Wkf, bq, bk);   // 0
    conv3_kernel<<<dim3((nbig + 255) / 256, 3), 256>>>(query, key_, value, nbig); // 1
    convw_kernel<<<dim3((nw + 255) / 256, 2), 256>>>(Wv, Wo, nw);                 // 2
    // merged q' / k' / V GEMMs (fp16 outputs)
    gemm_tc<<<4096, 256, GSMEM>>>(0, bv, nullptr, nullptr, mask);                 // 3

    kv_mma_kernel<<<dim3(KVCH, BHEADS), 128>>>();                                 // 4
    kv_reduce_kernel<<<BHEADS, 256>>>();                                          // 5
    ksum_reduce_kernel<<<(BHEADS * FDIM) / 256, 256>>>();                         // 6
    qkv_mma_kernel<<<dim3(MROWS / 128, NHEADS), 256>>>();                         // 7

    // out = attn @ Wo^T + bo
    gemm_tc<<<2048, 256, GSMEM>>>(1, nullptr, bo, out, mask);                     // 8
}